// round 9
// baseline (speedup 1.0000x reference)
#include <cuda_runtime.h>
#include <math.h>
#include <stdint.h>

#define NB 4
#define CIN 256
#define CO 256
#define HDIM 56
#define WDIM 56
#define HW 3136
#define NCOL 12544     // NB*HW
#define NHEAD 2
#define HD 128
#define EPS 1e-5f
#define SEH 16

// ---------------- scratch (device globals, no allocation) ----------------
__device__ float g_xt[NCOL * CIN];  // x transposed: [n][c]
__device__ float g_qt[NCOL * CO];   // [n][c]
__device__ float g_kt[NCOL * CO];
__device__ float g_vt[NCOL * CO];
__device__ float g_y1[NCOL * CO];   // attn out + BN1 + relu, [n][c]
__device__ float g_y2[NCOL * CO];   // agg out + BN2, [n][c]
__device__ float g_s [NB * SEH * HW]; // channel-major [b][j][hw]
__device__ float g_p [NB * SEH];
__device__ float g_g [NB * SEH];

// ---------------- helpers ----------------
__device__ __forceinline__ uint32_t f2tf32(float f) {
    uint32_t u;
    asm("cvt.rna.tf32.f32 %0, %1;" : "=r"(u) : "f"(f));
    return u;
}

__device__ __forceinline__ void mma_tf32(float* d, const uint32_t* a, const uint32_t* b) {
    asm volatile(
        "mma.sync.aligned.m16n8k8.row.col.f32.tf32.tf32.f32 "
        "{%0,%1,%2,%3}, {%4,%5,%6,%7}, {%8,%9}, {%0,%1,%2,%3};"
        : "+f"(d[0]), "+f"(d[1]), "+f"(d[2]), "+f"(d[3])
        : "r"(a[0]), "r"(a[1]), "r"(a[2]), "r"(a[3]), "r"(b[0]), "r"(b[1]));
}

// ---------------- transpose x: [b][c][hw] -> g_xt [b*hw][c] ----------------
__global__ void transpose_x_kernel(const float* __restrict__ x) {
    __shared__ float t[32][33];
    int b = blockIdx.z;
    int c0 = blockIdx.y * 32, p0 = blockIdx.x * 32;
    int tx = threadIdx.x, ty = threadIdx.y;   // 32 x 8
    const float* xb = x + ((size_t)b * CIN + c0) * HW + p0;
#pragma unroll
    for (int i = 0; i < 4; i++)
        t[ty * 4 + i][tx] = xb[(size_t)(ty * 4 + i) * HW + tx];
    __syncthreads();
    float* ob = g_xt + (size_t)(b * HW + p0) * CIN + c0;
#pragma unroll
    for (int i = 0; i < 4; i++)
        ob[(size_t)(ty * 4 + i) * CIN + tx] = t[tx][ty * 4 + i];
}

// ---------------- tensor-core tf32 GEMM, M64 x N128 tiles, 3 CTAs/SM -------
// D[o 64][n 128], K=256.  mode 0: qkv (z-selected), mode 1: agg (+BN2).
__global__ __launch_bounds__(256, 3) void gemm_mma_kernel(
    const float* __restrict__ Wq, const float* __restrict__ Wk,
    const float* __restrict__ Wv, const float* __restrict__ Wa,
    const float* __restrict__ g2, const float* __restrict__ b2,
    const float* __restrict__ m2, const float* __restrict__ v2,
    int mode)
{
    // union: 2 double-buffer chunks (2 x 12KB) OR epilogue staging (64x68 f32)
    __shared__ __align__(16) char smraw[24576];
    float* stg = (float*)smraw;

    int tid = threadIdx.x;
    int wid = tid >> 5, lane = tid & 31;
    int warpM = wid >> 2, warpN = wid & 3;       // 2 x 4 warp grid, warp tile 32x32
    int g = lane >> 2, t = lane & 3;

    const float* Wm;
    const float* Bsrc;
    float* outp;
    if (mode == 0) {
        int z = blockIdx.z;
        Wm   = (z == 0) ? Wq : (z == 1 ? Wk : Wv);
        outp = (z == 0) ? g_qt : (z == 1 ? g_kt : g_vt);
        Bsrc = g_xt;
    } else {
        Wm = Wa; Bsrc = g_y1; outp = g_y2;
    }
    int o0 = blockIdx.y * 64;
    int n0 = blockIdx.x * 128;

    float acc[2][4][4];
#pragma unroll
    for (int i = 0; i < 2; i++)
#pragma unroll
        for (int j = 0; j < 4; j++)
#pragma unroll
            for (int s = 0; s < 4; s++) acc[i][j][s] = 0.f;

    // producer roles: tid<64 -> A (64x16 chunk), tid 64..191 -> B (128x16)
    bool isA = tid < 64;
    bool isB = (tid >= 64) && (tid < 192);
    int t2 = isA ? tid : tid - 64;
    int low3 = t2 & 7;
    int midA = (t2 >> 3) & 3;            // A: mtile 0..3
    int midB = (t2 >> 3) & 7;            // B: 0..7
    int ktp = isA ? (t2 >> 5) : (t2 >> 6);   // 0..1
    const float* srcRow0 = Wm;           // init to something valid
    const float* srcRow1 = Wm;
    if (isA) {
        int rowA = o0 + midA * 16 + low3;
        srcRow0 = Wm + (size_t)rowA * 256;
        srcRow1 = srcRow0 + 8 * 256;
    } else if (isB) {
        int rowB = n0 + midB * 8 + low3;
        srcRow0 = Bsrc + (size_t)rowB * 256;
        srcRow1 = srcRow0 + 64 * 256;
    }
    int kOff = ktp * 8;

    float4 p0, p1, p2, p3;

#define LOADC(c) do { \
        if (isA || isB) { \
            int kb = (c) * 16 + kOff; \
            p0 = *(const float4*)(srcRow0 + kb); \
            p1 = *(const float4*)(srcRow0 + kb + 4); \
            p2 = *(const float4*)(srcRow1 + kb); \
            p3 = *(const float4*)(srcRow1 + kb + 4); \
        } \
    } while (0)

#define SCATTER(bufi) do { \
        if (isA) { \
            uint4* Ab = (uint4*)(smraw + (bufi) * 12288); \
            const float* e0 = &p0.x; const float* e1 = &p1.x; \
            const float* e2 = &p2.x; const float* e3 = &p3.x; \
            _Pragma("unroll") \
            for (int j = 0; j < 4; j++) { \
                int idx = (ktp * 4 + midA) * 32 + low3 * 4 + j; \
                idx ^= (idx >> 3) & 3; \
                Ab[idx] = make_uint4(f2tf32(e0[j]), f2tf32(e2[j]), \
                                     f2tf32(e1[j]), f2tf32(e3[j])); \
            } \
        } else if (isB) { \
            uint2* Bb = (uint2*)(smraw + (bufi) * 12288 + 4096); \
            const float* e0 = &p0.x; const float* e1 = &p1.x; \
            const float* e2 = &p2.x; const float* e3 = &p3.x; \
            _Pragma("unroll") \
            for (int j = 0; j < 4; j++) { \
                int idx = (ktp * 16 + midB) * 32 + low3 * 4 + j; \
                idx ^= (idx >> 4) & 3; \
                Bb[idx] = make_uint2(f2tf32(e0[j]), f2tf32(e1[j])); \
                int idx2 = (ktp * 16 + midB + 8) * 32 + low3 * 4 + j; \
                idx2 ^= (idx2 >> 4) & 3; \
                Bb[idx2] = make_uint2(f2tf32(e2[j]), f2tf32(e3[j])); \
            } \
        } \
    } while (0)

    LOADC(0);
    SCATTER(0);
    LOADC(1);
    __syncthreads();

    for (int c = 0; c < 16; c++) {
        if (c < 15) SCATTER((c + 1) & 1);
        if (c < 14) LOADC(c + 2);
        {
            const uint4* Ab = (const uint4*)(smraw + (c & 1) * 12288);
            const uint2* Bb = (const uint2*)(smraw + (c & 1) * 12288 + 4096);
#pragma unroll
            for (int ks = 0; ks < 2; ks++) {
                uint32_t af[2][4], bf[4][2];
#pragma unroll
                for (int mt = 0; mt < 2; mt++) {
                    int idx = (ks * 4 + warpM * 2 + mt) * 32 + lane;
                    idx ^= (idx >> 3) & 3;
                    uint4 v = Ab[idx];
                    af[mt][0] = v.x; af[mt][1] = v.y; af[mt][2] = v.z; af[mt][3] = v.w;
                }
#pragma unroll
                for (int nt = 0; nt < 4; nt++) {
                    int idx = (ks * 16 + warpN * 4 + nt) * 32 + lane;
                    idx ^= (idx >> 4) & 3;
                    uint2 v = Bb[idx];
                    bf[nt][0] = v.x; bf[nt][1] = v.y;
                }
#pragma unroll
                for (int mt = 0; mt < 2; mt++)
#pragma unroll
                    for (int nt = 0; nt < 4; nt++)
                        mma_tf32(acc[mt][nt], af[mt], bf[nt]);
            }
        }
        __syncthreads();
    }

    // epilogue: stage [n_local 64][o_local 64(+4 pad)] halves, coalesced store
    int h_of_warp = warpN >> 1;
    for (int h = 0; h < 2; h++) {
        __syncthreads();
        if (h_of_warp == h) {
#pragma unroll
            for (int mt = 0; mt < 2; mt++)
#pragma unroll
                for (int nt = 0; nt < 4; nt++)
#pragma unroll
                    for (int s = 0; s < 4; s++) {
                        int ol = warpM * 32 + mt * 16 + g + (s >> 1) * 8;
                        int nl = (warpN & 1) * 32 + nt * 8 + 2 * t + (s & 1);
                        stg[nl * 68 + ol] = acc[mt][nt][s];
                    }
        }
        __syncthreads();
#pragma unroll
        for (int i = 0; i < 4; i++) {
            int idx = tid + 256 * i;
            int nl = idx >> 4, o4 = idx & 15;
            float4 v = *(float4*)&stg[nl * 68 + o4 * 4];
            if (mode == 1) {
                int ob = o0 + o4 * 4;
                float4 gg = *(const float4*)&g2[ob];
                float4 bb = *(const float4*)&b2[ob];
                float4 mm = *(const float4*)&m2[ob];
                float4 vv = *(const float4*)&v2[ob];
                float s0 = gg.x * rsqrtf(vv.x + EPS);
                float s1 = gg.y * rsqrtf(vv.y + EPS);
                float s2 = gg.z * rsqrtf(vv.z + EPS);
                float s3 = gg.w * rsqrtf(vv.w + EPS);
                v.x = v.x * s0 + (bb.x - mm.x * s0);
                v.y = v.y * s1 + (bb.y - mm.y * s1);
                v.z = v.z * s2 + (bb.z - mm.z * s2);
                v.w = v.w * s3 + (bb.w - mm.w * s3);
            }
            *(float4*)&outp[(size_t)(n0 + h * 64 + nl) * 256 + o0 + o4 * 4] = v;
        }
    }
#undef LOADC
#undef SCATTER
}

// ---------------- attention: CTA per (b, head, 4x4 pixel tile) --------------
// smem-tiled: k tile (8x8 with halo) staged, then overwritten by v tile.
// OOB positions are zero-filled, which exactly reproduces the reference's
// zero-padded k/v (+rel bias on scores, 0 contribution from v).
__global__ __launch_bounds__(256) void attn_kernel(
                            const float* __restrict__ rel_h,
                            const float* __restrict__ rel_w,
                            const float* __restrict__ g1, const float* __restrict__ b1,
                            const float* __restrict__ m1, const float* __restrict__ v1) {
    __shared__ __align__(16) float kv[64][128];   // 32 KB tile (k then v)
    __shared__ float attnw[16][26];
    __shared__ __align__(16) float relS[5][128];

    int tid = threadIdx.x, wid = tid >> 5, lane = tid & 31;
    int tile = blockIdx.x;           // 0..195
    int th = tile / 14, tw = tile % 14;
    int nh = blockIdx.y, b = blockIdx.z;
    int h0 = th * 4, w0 = tw * 4;

    // cache rel bias table as [tap][c]
    const float* rel = nh ? rel_w : rel_h;   // [c][tap], 128*5
    for (int i = tid; i < 640; i += 256) {
        int c = i / 5, tp = i % 5;
        relS[tp][c] = rel[i];
    }

    // ---- load k tile (8x8 halo positions x 128 ch) ----
    const float* kbase = g_kt + (size_t)b * HW * CO + nh * HD;
#pragma unroll
    for (int i = 0; i < 8; i++) {
        int idx = tid + 256 * i;
        int pos = idx >> 5, c4 = idx & 31;
        int py = pos >> 3, px = pos & 7;
        int hh = h0 - 2 + py, ww = w0 - 2 + px;
        float4 v = make_float4(0.f, 0.f, 0.f, 0.f);
        if ((unsigned)hh < HDIM && (unsigned)ww < WDIM)
            v = *(const float4*)&kbase[(size_t)(hh * WDIM + ww) * CO + c4 * 4];
        *(float4*)&kv[pos][c4 * 4] = v;
    }
    __syncthreads();

    // ---- phase 1: scores + softmax (2 pixels per warp) ----
#pragma unroll
    for (int pp = 0; pp < 2; pp++) {
        int pi = wid * 2 + pp;
        int py = pi >> 2, px = pi & 3;
        int hw = (h0 + py) * WDIM + (w0 + px);
        const float4 q4 = *(const float4*)&g_qt[(size_t)(b * HW + hw) * CO + nh * HD + lane * 4];

        float bias[5];
#pragma unroll
        for (int tp = 0; tp < 5; tp++) {
            float4 r4 = *(const float4*)&relS[tp][lane * 4];
            float p = q4.x * r4.x + q4.y * r4.y + q4.z * r4.z + q4.w * r4.w;
#pragma unroll
            for (int m = 16; m; m >>= 1) p += __shfl_xor_sync(0xffffffffu, p, m);
            bias[tp] = p;
        }

        float sc_mine = -1e30f;   // lane i (<25) keeps score i
#pragma unroll
        for (int t25 = 0; t25 < 25; t25++) {
            int ki = t25 / 5, kj = t25 % 5;
            int pos = (py + ki) * 8 + px + kj;
            float4 k4 = *(const float4*)&kv[pos][lane * 4];
            float p = q4.x * k4.x + q4.y * k4.y + q4.z * k4.z + q4.w * k4.w;
#pragma unroll
            for (int m = 16; m; m >>= 1) p += __shfl_xor_sync(0xffffffffu, p, m);
            float s = (p + bias[nh ? kj : ki]) * 0.08838834764831845f;
            if (lane == t25) sc_mine = s;
        }
        float mx = sc_mine;
#pragma unroll
        for (int m = 16; m; m >>= 1) mx = fmaxf(mx, __shfl_xor_sync(0xffffffffu, mx, m));
        float e = (lane < 25) ? __expf(sc_mine - mx) : 0.f;
        float ssum = e;
#pragma unroll
        for (int m = 16; m; m >>= 1) ssum += __shfl_xor_sync(0xffffffffu, ssum, m);
        if (lane < 25) attnw[pi][lane] = e / ssum;
    }
    __syncthreads();

    // ---- overwrite tile with v ----
    const float* vbase = g_vt + (size_t)b * HW * CO + nh * HD;
#pragma unroll
    for (int i = 0; i < 8; i++) {
        int idx = tid + 256 * i;
        int pos = idx >> 5, c4 = idx & 31;
        int py = pos >> 3, px = pos & 7;
        int hh = h0 - 2 + py, ww = w0 - 2 + px;
        float4 v = make_float4(0.f, 0.f, 0.f, 0.f);
        if ((unsigned)hh < HDIM && (unsigned)ww < WDIM)
            v = *(const float4*)&vbase[(size_t)(hh * WDIM + ww) * CO + c4 * 4];
        *(float4*)&kv[pos][c4 * 4] = v;
    }
    __syncthreads();

    // ---- phase 2: weighted sum + BN1 + relu ----
#pragma unroll
    for (int pp = 0; pp < 2; pp++) {
        int pi = wid * 2 + pp;
        int py = pi >> 2, px = pi & 3;
        int hw = (h0 + py) * WDIM + (w0 + px);
        float4 acc = make_float4(0.f, 0.f, 0.f, 0.f);
#pragma unroll
        for (int t25 = 0; t25 < 25; t25++) {
            int ki = t25 / 5, kj = t25 % 5;
            int pos = (py + ki) * 8 + px + kj;
            float a = attnw[pi][t25];
            float4 v4 = *(const float4*)&kv[pos][lane * 4];
            acc.x += a * v4.x; acc.y += a * v4.y; acc.z += a * v4.z; acc.w += a * v4.w;
        }
        int ch0 = nh * HD + lane * 4;
        float av[4] = {acc.x, acc.y, acc.z, acc.w};
        float4 ov;
        float* pv = &ov.x;
#pragma unroll
        for (int i = 0; i < 4; i++) {
            int ch = ch0 + i;
            float scl = g1[ch] * rsqrtf(v1[ch] + EPS);
            pv[i] = fmaxf((av[i] - m1[ch]) * scl + b1[ch], 0.f);
        }
        *(float4*)&g_y1[(size_t)(b * HW + hw) * CO + ch0] = ov;
    }
}

// ---------------- zero p accumulator ----------------
__global__ void zero_p_kernel() {
    if (threadIdx.x < NB * SEH) g_p[threadIdx.x] = 0.f;
}

// ---------------- SE stage 1: warp per pixel over n-major y2 ----------------
__global__ __launch_bounds__(256) void se1_kernel(const float* __restrict__ Win,
                           const float* __restrict__ gin, const float* __restrict__ bin,
                           const float* __restrict__ min_, const float* __restrict__ vin) {
    __shared__ float Ws[SEH * CO];
    __shared__ float pool[SEH];
    int tid = threadIdx.x, wid = tid >> 5, lane = tid & 31;
    for (int i = tid; i < SEH * CO; i += 256) Ws[i] = Win[i];
    if (tid < SEH) pool[tid] = 0.f;
    __syncthreads();

    int n0 = blockIdx.x * 64;
    int bb = n0 / HW;
    int hwb = n0 % HW;

    float scl = 0.f, bo = 0.f;
    if (lane < SEH) {
        scl = gin[lane] * rsqrtf(vin[lane] + EPS);
        bo = bin[lane] - min_[lane] * scl;
    }

    for (int px = wid; px < 64; px += 8) {
        const float* y = &g_y2[(size_t)(n0 + px) * CO];
        float4 v0 = *(const float4*)&y[lane * 4];
        float4 v1 = *(const float4*)&y[128 + lane * 4];
        float sj_me = 0.f;
#pragma unroll
        for (int j = 0; j < SEH; j++) {
            const float* wj = &Ws[j * CO];
            float4 w0 = *(const float4*)&wj[lane * 4];
            float4 w1 = *(const float4*)&wj[128 + lane * 4];
            float p = v0.x * w0.x + v0.y * w0.y + v0.z * w0.z + v0.w * w0.w
                    + v1.x * w1.x + v1.y * w1.y + v1.z * w1.z + v1.w * w1.w;
#pragma unroll
            for (int m = 16; m; m >>= 1) p += __shfl_xor_sync(0xffffffffu, p, m);
            if (lane == j) sj_me = p;
        }
        if (lane < SEH) {
            float sv = fmaxf(sj_me * scl + bo, 0.f);
            g_s[(size_t)bb * SEH * HW + (size_t)lane * HW + (hwb + px)] = sv;
            atomicAdd(&pool[lane], sv);
        }
    }
    __syncthreads();
    if (tid < SEH) atomicAdd(&g_p[bb * SEH + tid], pool[tid]);
}

// ---------------- SE stage 2: gates ----------------
__global__ void se2_kernel(const float* __restrict__ fc1, const float* __restrict__ fc2) {
    int tid = threadIdx.x;
    if (tid < NB * SEH) {
        int bb = tid >> 4, i = tid & 15;
        float hsum = 0.f;
#pragma unroll
        for (int j = 0; j < SEH; j++) hsum += (g_p[bb * SEH + j] * (1.f / HW)) * fc1[j];
        float hid = fmaxf(hsum, 0.f);
        g_g[tid] = 1.f / (1.f + __expf(-(hid * fc2[i])));
    }
}

// ---------------- SE stage 3: out = BN(se_Wout @ (s * g)), channel-major ----
__global__ void se3_kernel(const float* __restrict__ Wout,
                           const float* __restrict__ gout, const float* __restrict__ bout,
                           const float* __restrict__ mout, const float* __restrict__ vout,
                           float* __restrict__ out) {
    __shared__ float sjs[SEH][16];
    int tid = threadIdx.x;
    int n0 = blockIdx.x * 16;
    int bb = n0 / HW;
    int hw0 = n0 % HW;

    int j = tid >> 4, nn = tid & 15;
    sjs[j][nn] = g_s[(size_t)bb * SEH * HW + (size_t)j * HW + hw0 + nn] * g_g[bb * SEH + j];
    __syncthreads();

    int o = tid;
    float wreg[SEH];
#pragma unroll
    for (int jj = 0; jj < SEH; jj++) wreg[jj] = Wout[o * SEH + jj];
    float scl = gout[o] * rsqrtf(vout[o] + EPS);
    float bo = bout[o] - mout[o] * scl;
    float* op = out + (size_t)bb * CO * HW + (size_t)o * HW + hw0;
#pragma unroll
    for (int nq = 0; nq < 4; nq++) {
        float4 a = make_float4(0.f, 0.f, 0.f, 0.f);
#pragma unroll
        for (int jj = 0; jj < SEH; jj++) {
            float wv = wreg[jj];
            a.x += wv * sjs[jj][nq * 4 + 0];
            a.y += wv * sjs[jj][nq * 4 + 1];
            a.z += wv * sjs[jj][nq * 4 + 2];
            a.w += wv * sjs[jj][nq * 4 + 3];
        }
        float4 r;
        r.x = a.x * scl + bo; r.y = a.y * scl + bo;
        r.z = a.z * scl + bo; r.w = a.w * scl + bo;
        *(float4*)&op[nq * 4] = r;
    }
}

// ---------------- launch ----------------
extern "C" void kernel_launch(void* const* d_in, const int* in_sizes, int n_in,
                              void* d_out, int out_size) {
    const float* x       = (const float*)d_in[0];
    const float* Wq      = (const float*)d_in[1];
    const float* Wk      = (const float*)d_in[2];
    const float* Wv      = (const float*)d_in[3];
    const float* rel_h   = (const float*)d_in[4];
    const float* rel_w   = (const float*)d_in[5];
    const float* agg_g1  = (const float*)d_in[6];
    const float* agg_b1  = (const float*)d_in[7];
    const float* agg_m1  = (const float*)d_in[8];
    const float* agg_v1  = (const float*)d_in[9];
    const float* agg_W   = (const float*)d_in[10];
    const float* agg_g2  = (const float*)d_in[11];
    const float* agg_b2  = (const float*)d_in[12];
    const float* agg_m2  = (const float*)d_in[13];
    const float* agg_v2  = (const float*)d_in[14];
    const float* se_Win  = (const float*)d_in[15];
    const float* se_g_in = (const float*)d_in[16];
    const float* se_b_in = (const float*)d_in[17];
    const float* se_m_in = (const float*)d_in[18];
    const float* se_v_in = (const float*)d_in[19];
    const float* se_fc1  = (const float*)d_in[20];
    const float* se_fc2  = (const float*)d_in[21];
    const float* se_Wout = (const float*)d_in[22];
    const float* se_g_out= (const float*)d_in[23];
    const float* se_b_out= (const float*)d_in[24];
    const float* se_m_out= (const float*)d_in[25];
    const float* se_v_out= (const float*)d_in[26];
    float* out = (float*)d_out;

    transpose_x_kernel<<<dim3(98, 8, 4), dim3(32, 8)>>>(x);

    gemm_mma_kernel<<<dim3(98, 4, 3), 256>>>(Wq, Wk, Wv, nullptr,
                                             nullptr, nullptr, nullptr, nullptr, 0);

    attn_kernel<<<dim3(196, NHEAD, NB), 256>>>(rel_h, rel_w, agg_g1, agg_b1, agg_m1, agg_v1);

    gemm_mma_kernel<<<dim3(98, 4, 1), 256>>>(nullptr, nullptr, nullptr, agg_W,
                                             agg_g2, agg_b2, agg_m2, agg_v2, 1);

    zero_p_kernel<<<1, 64>>>();
    se1_kernel<<<NCOL / 64, 256>>>(se_Win, se_g_in, se_b_in, se_m_in, se_v_in);
    se2_kernel<<<1, 64>>>(se_fc1, se_fc2);
    se3_kernel<<<NCOL / 16, 256>>>(se_Wout, se_g_out, se_b_out, se_m_out, se_v_out, out);
}

// round 11
// speedup vs baseline: 1.3884x; 1.3884x over previous
#include <cuda_runtime.h>
#include <math.h>
#include <stdint.h>

#define NB 4
#define CIN 256
#define CO 256
#define HDIM 56
#define WDIM 56
#define HW 3136
#define NCOL 12544     // NB*HW
#define NHEAD 2
#define HD 128
#define EPS 1e-5f
#define SEH 16
#define NPAN 98        // NCOL/128
#define CHUNKW 2048    // u32 per 128x16 chunk image

// ---------------- scratch (device globals, no allocation) ----------------
__device__ uint32_t g_Wp [4 * 2 * 16 * CHUNKW];   // weight A-panels (tf32 frag layout)
__device__ uint32_t g_xtp[NPAN * 16 * CHUNKW];    // x B-panels
__device__ uint32_t g_y1p[NPAN * 16 * CHUNKW];    // y1 B-panels
__device__ float g_qt[NCOL * CO];   // [n][c]
__device__ float g_kt[NCOL * CO];
__device__ float g_vt[NCOL * CO];
__device__ float g_y2[NCOL * CO];   // agg out + BN2, [n][c]
__device__ float g_s [NB * SEH * HW]; // channel-major [b][j][hw]
__device__ float g_p [NB * SEH];
__device__ float g_g [NB * SEH];

// ---------------- helpers ----------------
__device__ __forceinline__ uint32_t f2tf32(float f) {
    uint32_t u;
    asm("cvt.rna.tf32.f32 %0, %1;" : "=r"(u) : "f"(f));
    return u;
}
__device__ __forceinline__ uint32_t smem_u32(const void* p) {
    uint32_t a;
    asm("{ .reg .u64 t; cvta.to.shared.u64 t, %1; cvt.u32.u64 %0, t; }" : "=r"(a) : "l"(p));
    return a;
}
__device__ __forceinline__ void cpasync16(uint32_t smem, const void* g) {
    asm volatile("cp.async.cg.shared.global [%0], [%1], 16;" :: "r"(smem), "l"(g));
}
__device__ __forceinline__ void mma_tf32(float* d, const uint32_t* a, const uint32_t* b) {
    asm volatile(
        "mma.sync.aligned.m16n8k8.row.col.f32.tf32.tf32.f32 "
        "{%0,%1,%2,%3}, {%4,%5,%6,%7}, {%8,%9}, {%0,%1,%2,%3};"
        : "+f"(d[0]), "+f"(d[1]), "+f"(d[2]), "+f"(d[3])
        : "r"(a[0]), "r"(a[1]), "r"(a[2]), "r"(a[3]), "r"(b[0]), "r"(b[1]));
}

// A-image u32 offset within one 128x16 chunk (m rows x k cols)
__device__ __forceinline__ int a_off(int m, int k) {
    int ks = k >> 3, mtile = m >> 4, mi = m & 15;
    int lane = (mi & 7) * 4 + (k & 3);
    int slot = (mi >> 3) + 2 * ((k >> 2) & 1);
    int I = (ks * 8 + mtile) * 32 + lane;
    I ^= (I >> 3) & 3;
    return I * 4 + slot;
}
// B-image u32 offset within one 128x16 chunk (n rows x k cols)
__device__ __forceinline__ int b_off(int n, int k) {
    int ks = k >> 3, ntile = n >> 3;
    int lane = (n & 7) * 4 + (k & 3);
    int slot = (k >> 2) & 1;
    int I = (ks * 16 + ntile) * 32 + lane;
    I ^= (I >> 4) & 3;
    return I * 2 + slot;
}

// ---------------- weight repack: 4 matrices -> A-panels ----------------
__global__ void repack_w_kernel(const float* __restrict__ Wq, const float* __restrict__ Wk,
                                const float* __restrict__ Wv, const float* __restrict__ Wa) {
    int v = blockIdx.x * 256 + threadIdx.x;    // 4*256*256 values
    int mat = v >> 16;
    int rem = v & 65535;
    int o = rem >> 8, c = rem & 255;
    const float* W = (mat == 0) ? Wq : (mat == 1 ? Wk : (mat == 2 ? Wv : Wa));
    uint32_t u = f2tf32(W[o * 256 + c]);
    g_Wp[(((size_t)mat * 2 + (o >> 7)) * 16 + (c >> 4)) * CHUNKW + a_off(o & 127, c & 15)] = u;
}

// ---------------- transpose x: [b][c][hw] -> B-panels ----------------
__global__ void transpose_x_kernel(const float* __restrict__ x) {
    __shared__ float t[32][33];
    int b = blockIdx.z;
    int c0 = blockIdx.y * 32, p0 = blockIdx.x * 32;
    int tx = threadIdx.x, ty = threadIdx.y;   // 32 x 8
    const float* xb = x + ((size_t)b * CIN + c0) * HW + p0;
#pragma unroll
    for (int i = 0; i < 4; i++)
        t[ty * 4 + i][tx] = xb[(size_t)(ty * 4 + i) * HW + tx];
    __syncthreads();
    // value t[tx][ty*4+i] = x[c0+tx][p0+ty*4+i]  -> channel c0+tx, pixel p0+ty*4+i
    int c = c0 + tx;
#pragma unroll
    for (int i = 0; i < 4; i++) {
        int nglob = b * HW + p0 + ty * 4 + i;
        int ntile = nglob >> 7, nn = nglob & 127;
        g_xtp[((size_t)ntile * 16 + (c >> 4)) * CHUNKW + b_off(nn, c & 15)]
            = f2tf32(t[tx][ty * 4 + i]);
    }
}

// ---------------- tensor-core tf32 GEMM, cp.async 3-stage, M128 x N128 -----
// mode 0: qkv (z selects matrix 0..2, B=g_xtp, out flat [n][c])
// mode 1: agg (matrix 3, B=g_y1p, out g_y2 with BN2)
__global__ __launch_bounds__(256, 2) void gemm_mma_kernel(
    const float* __restrict__ g2, const float* __restrict__ b2,
    const float* __restrict__ m2, const float* __restrict__ v2,
    int mode)
{
    __shared__ __align__(16) char smraw[49152];   // 3 stages x 16KB; union epi staging
    float* stg = (float*)smraw;

    int tid = threadIdx.x;
    int wid = tid >> 5, lane = tid & 31;
    int warpM = wid >> 2, warpN = wid & 3;       // 2 x 4 warps, warp tile 64x32
    int g = lane >> 2, t = lane & 3;

    int mat;
    const uint32_t* Bbase;
    float* outp;
    if (mode == 0) {
        mat = blockIdx.z;
        Bbase = g_xtp;
        outp = (mat == 0) ? g_qt : (mat == 1 ? g_kt : g_vt);
    } else {
        mat = 3; Bbase = g_y1p; outp = g_y2;
    }
    int o0 = blockIdx.y * 128;
    int n0 = blockIdx.x * 128;

    const uint4* Apan = (const uint4*)&g_Wp[((size_t)mat * 2 + blockIdx.y) * 16 * CHUNKW];
    const uint4* Bpan = (const uint4*)&Bbase[(size_t)blockIdx.x * 16 * CHUNKW];
    uint32_t smb = smem_u32(smraw);

    float acc[4][4][4];
#pragma unroll
    for (int i = 0; i < 4; i++)
#pragma unroll
        for (int j = 0; j < 4; j++)
#pragma unroll
            for (int s = 0; s < 4; s++) acc[i][j][s] = 0.f;

#define ISSUE(c, s) do { \
        uint32_t dst = smb + (s) * 16384; \
        const uint4* sa = Apan + (c) * 512; \
        const uint4* sb = Bpan + (c) * 512; \
        cpasync16(dst + tid * 16,                sa + tid); \
        cpasync16(dst + (tid + 256) * 16,        sa + tid + 256); \
        cpasync16(dst + 8192 + tid * 16,         sb + tid); \
        cpasync16(dst + 8192 + (tid + 256) * 16, sb + tid + 256); \
        asm volatile("cp.async.commit_group;"); \
    } while (0)

    ISSUE(0, 0);
    ISSUE(1, 1);

    for (int c = 0; c < 16; c++) {
        if (c < 15) asm volatile("cp.async.wait_group 1;");
        else        asm volatile("cp.async.wait_group 0;");
        __syncthreads();
        if (c + 2 < 16) ISSUE(c + 2, (c + 2) % 3);

        const uint4* Ab = (const uint4*)(smraw + (c % 3) * 16384);
        const uint2* Bb = (const uint2*)(smraw + (c % 3) * 16384 + 8192);
#pragma unroll
        for (int ks = 0; ks < 2; ks++) {
            uint32_t af[4][4], bf[4][2];
#pragma unroll
            for (int mt = 0; mt < 4; mt++) {
                int idx = (ks * 8 + warpM * 4 + mt) * 32 + lane;
                idx ^= (idx >> 3) & 3;
                uint4 v = Ab[idx];
                af[mt][0] = v.x; af[mt][1] = v.y; af[mt][2] = v.z; af[mt][3] = v.w;
            }
#pragma unroll
            for (int nt = 0; nt < 4; nt++) {
                int idx = (ks * 16 + warpN * 4 + nt) * 32 + lane;
                idx ^= (idx >> 4) & 3;
                uint2 v = Bb[idx];
                bf[nt][0] = v.x; bf[nt][1] = v.y;
            }
#pragma unroll
            for (int mt = 0; mt < 4; mt++)
#pragma unroll
                for (int nt = 0; nt < 4; nt++)
                    mma_tf32(acc[mt][nt], af[mt], bf[nt]);
        }
        __syncthreads();
    }
#undef ISSUE

    // epilogue: stage [n_local 64][o_local 128(+4)] halves, coalesced [n][o] store
    int h_of_warp = warpN >> 1;
    for (int h = 0; h < 2; h++) {
        __syncthreads();
        if (h_of_warp == h) {
#pragma unroll
            for (int mt = 0; mt < 4; mt++)
#pragma unroll
                for (int nt = 0; nt < 4; nt++)
#pragma unroll
                    for (int s = 0; s < 4; s++) {
                        int ol = warpM * 64 + mt * 16 + g + (s >> 1) * 8;
                        int nl = (warpN & 1) * 32 + nt * 8 + 2 * t + (s & 1);
                        stg[nl * 132 + ol] = acc[mt][nt][s];
                    }
        }
        __syncthreads();
#pragma unroll
        for (int i = 0; i < 8; i++) {
            int idx = tid + 256 * i;
            int nl = idx >> 5, o4 = idx & 31;
            float4 v = *(float4*)&stg[nl * 132 + o4 * 4];
            if (mode == 1) {
                int ob = o0 + o4 * 4;
                float4 gg = *(const float4*)&g2[ob];
                float4 bb = *(const float4*)&b2[ob];
                float4 mm = *(const float4*)&m2[ob];
                float4 vv = *(const float4*)&v2[ob];
                float s0 = gg.x * rsqrtf(vv.x + EPS);
                float s1 = gg.y * rsqrtf(vv.y + EPS);
                float s2 = gg.z * rsqrtf(vv.z + EPS);
                float s3 = gg.w * rsqrtf(vv.w + EPS);
                v.x = v.x * s0 + (bb.x - mm.x * s0);
                v.y = v.y * s1 + (bb.y - mm.y * s1);
                v.z = v.z * s2 + (bb.z - mm.z * s2);
                v.w = v.w * s3 + (bb.w - mm.w * s3);
            }
            *(float4*)&outp[(size_t)(n0 + h * 64 + nl) * 256 + o0 + o4 * 4] = v;
        }
    }
}

// ---------------- attention: CTA per (b, head, 4x4 pixel tile) --------------
// y1 output goes straight into B-panel fragment layout (tf32-rounded).
__global__ __launch_bounds__(256) void attn_kernel(
                            const float* __restrict__ rel_h,
                            const float* __restrict__ rel_w,
                            const float* __restrict__ g1, const float* __restrict__ b1,
                            const float* __restrict__ m1, const float* __restrict__ v1) {
    __shared__ __align__(16) float kv[64][128];   // 32 KB tile (k then v)
    __shared__ float attnw[16][26];
    __shared__ __align__(16) float relS[5][128];

    int tid = threadIdx.x, wid = tid >> 5, lane = tid & 31;
    int tile = blockIdx.x;           // 0..195
    int th = tile / 14, tw = tile % 14;
    int nh = blockIdx.y, b = blockIdx.z;
    int h0 = th * 4, w0 = tw * 4;

    const float* rel = nh ? rel_w : rel_h;   // [c][tap], 128*5
    for (int i = tid; i < 640; i += 256) {
        int c = i / 5, tp = i % 5;
        relS[tp][c] = rel[i];
    }

    // ---- load k tile ----
    const float* kbase = g_kt + (size_t)b * HW * CO + nh * HD;
#pragma unroll
    for (int i = 0; i < 8; i++) {
        int idx = tid + 256 * i;
        int pos = idx >> 5, c4 = idx & 31;
        int py = pos >> 3, px = pos & 7;
        int hh = h0 - 2 + py, ww = w0 - 2 + px;
        float4 v = make_float4(0.f, 0.f, 0.f, 0.f);
        if ((unsigned)hh < HDIM && (unsigned)ww < WDIM)
            v = *(const float4*)&kbase[(size_t)(hh * WDIM + ww) * CO + c4 * 4];
        *(float4*)&kv[pos][c4 * 4] = v;
    }
    __syncthreads();

    // ---- phase 1: scores + softmax ----
#pragma unroll
    for (int pp = 0; pp < 2; pp++) {
        int pi = wid * 2 + pp;
        int py = pi >> 2, px = pi & 3;
        int hw = (h0 + py) * WDIM + (w0 + px);
        const float4 q4 = *(const float4*)&g_qt[(size_t)(b * HW + hw) * CO + nh * HD + lane * 4];

        float bias[5];
#pragma unroll
        for (int tp = 0; tp < 5; tp++) {
            float4 r4 = *(const float4*)&relS[tp][lane * 4];
            float p = q4.x * r4.x + q4.y * r4.y + q4.z * r4.z + q4.w * r4.w;
#pragma unroll
            for (int m = 16; m; m >>= 1) p += __shfl_xor_sync(0xffffffffu, p, m);
            bias[tp] = p;
        }

        float sc_mine = -1e30f;
#pragma unroll
        for (int t25 = 0; t25 < 25; t25++) {
            int ki = t25 / 5, kj = t25 % 5;
            int pos = (py + ki) * 8 + px + kj;
            float4 k4 = *(const float4*)&kv[pos][lane * 4];
            float p = q4.x * k4.x + q4.y * k4.y + q4.z * k4.z + q4.w * k4.w;
#pragma unroll
            for (int m = 16; m; m >>= 1) p += __shfl_xor_sync(0xffffffffu, p, m);
            float s = (p + bias[nh ? kj : ki]) * 0.08838834764831845f;
            if (lane == t25) sc_mine = s;
        }
        float mx = sc_mine;
#pragma unroll
        for (int m = 16; m; m >>= 1) mx = fmaxf(mx, __shfl_xor_sync(0xffffffffu, mx, m));
        float e = (lane < 25) ? __expf(sc_mine - mx) : 0.f;
        float ssum = e;
#pragma unroll
        for (int m = 16; m; m >>= 1) ssum += __shfl_xor_sync(0xffffffffu, ssum, m);
        if (lane < 25) attnw[pi][lane] = e / ssum;
    }
    __syncthreads();

    // ---- overwrite tile with v ----
    const float* vbase = g_vt + (size_t)b * HW * CO + nh * HD;
#pragma unroll
    for (int i = 0; i < 8; i++) {
        int idx = tid + 256 * i;
        int pos = idx >> 5, c4 = idx & 31;
        int py = pos >> 3, px = pos & 7;
        int hh = h0 - 2 + py, ww = w0 - 2 + px;
        float4 v = make_float4(0.f, 0.f, 0.f, 0.f);
        if ((unsigned)hh < HDIM && (unsigned)ww < WDIM)
            v = *(const float4*)&vbase[(size_t)(hh * WDIM + ww) * CO + c4 * 4];
        *(float4*)&kv[pos][c4 * 4] = v;
    }
    __syncthreads();

    // ---- phase 2: weighted sum + BN1 + relu -> panel store ----
#pragma unroll
    for (int pp = 0; pp < 2; pp++) {
        int pi = wid * 2 + pp;
        int py = pi >> 2, px = pi & 3;
        int hw = (h0 + py) * WDIM + (w0 + px);
        float4 acc = make_float4(0.f, 0.f, 0.f, 0.f);
#pragma unroll
        for (int t25 = 0; t25 < 25; t25++) {
            int ki = t25 / 5, kj = t25 % 5;
            int pos = (py + ki) * 8 + px + kj;
            float a = attnw[pi][t25];
            float4 v4 = *(const float4*)&kv[pos][lane * 4];
            acc.x += a * v4.x; acc.y += a * v4.y; acc.z += a * v4.z; acc.w += a * v4.w;
        }
        int ch0 = nh * HD + lane * 4;
        int nglob = b * HW + hw;
        int ntile = nglob >> 7, nn = nglob & 127;
        float av[4] = {acc.x, acc.y, acc.z, acc.w};
#pragma unroll
        for (int i = 0; i < 4; i++) {
            int ch = ch0 + i;
            float scl = g1[ch] * rsqrtf(v1[ch] + EPS);
            float val = fmaxf((av[i] - m1[ch]) * scl + b1[ch], 0.f);
            g_y1p[((size_t)ntile * 16 + (ch >> 4)) * CHUNKW + b_off(nn, ch & 15)] = f2tf32(val);
        }
    }
}

// ---------------- zero p accumulator ----------------
__global__ void zero_p_kernel() {
    if (threadIdx.x < NB * SEH) g_p[threadIdx.x] = 0.f;
}

// ---------------- SE stage 1 ----------------
__global__ __launch_bounds__(256) void se1_kernel(const float* __restrict__ Win,
                           const float* __restrict__ gin, const float* __restrict__ bin,
                           const float* __restrict__ min_, const float* __restrict__ vin) {
    __shared__ float Ws[SEH * CO];
    __shared__ float pool[SEH];
    int tid = threadIdx.x, wid = tid >> 5, lane = tid & 31;
    for (int i = tid; i < SEH * CO; i += 256) Ws[i] = Win[i];
    if (tid < SEH) pool[tid] = 0.f;
    __syncthreads();

    int n0 = blockIdx.x * 64;
    int bb = n0 / HW;
    int hwb = n0 % HW;

    float scl = 0.f, bo = 0.f;
    if (lane < SEH) {
        scl = gin[lane] * rsqrtf(vin[lane] + EPS);
        bo = bin[lane] - min_[lane] * scl;
    }

    for (int px = wid; px < 64; px += 8) {
        const float* y = &g_y2[(size_t)(n0 + px) * CO];
        float4 v0 = *(const float4*)&y[lane * 4];
        float4 v1 = *(const float4*)&y[128 + lane * 4];
        float sj_me = 0.f;
#pragma unroll
        for (int j = 0; j < SEH; j++) {
            const float* wj = &Ws[j * CO];
            float4 w0 = *(const float4*)&wj[lane * 4];
            float4 w1 = *(const float4*)&wj[128 + lane * 4];
            float p = v0.x * w0.x + v0.y * w0.y + v0.z * w0.z + v0.w * w0.w
                    + v1.x * w1.x + v1.y * w1.y + v1.z * w1.z + v1.w * w1.w;
#pragma unroll
            for (int m = 16; m; m >>= 1) p += __shfl_xor_sync(0xffffffffu, p, m);
            if (lane == j) sj_me = p;
        }
        if (lane < SEH) {
            float sv = fmaxf(sj_me * scl + bo, 0.f);
            g_s[(size_t)bb * SEH * HW + (size_t)lane * HW + (hwb + px)] = sv;
            atomicAdd(&pool[lane], sv);
        }
    }
    __syncthreads();
    if (tid < SEH) atomicAdd(&g_p[bb * SEH + tid], pool[tid]);
}

// ---------------- SE stage 2 ----------------
__global__ void se2_kernel(const float* __restrict__ fc1, const float* __restrict__ fc2) {
    int tid = threadIdx.x;
    if (tid < NB * SEH) {
        int bb = tid >> 4, i = tid & 15;
        float hsum = 0.f;
#pragma unroll
        for (int j = 0; j < SEH; j++) hsum += (g_p[bb * SEH + j] * (1.f / HW)) * fc1[j];
        float hid = fmaxf(hsum, 0.f);
        g_g[tid] = 1.f / (1.f + __expf(-(hid * fc2[i])));
    }
}

// ---------------- SE stage 3 ----------------
__global__ void se3_kernel(const float* __restrict__ Wout,
                           const float* __restrict__ gout, const float* __restrict__ bout,
                           const float* __restrict__ mout, const float* __restrict__ vout,
                           float* __restrict__ out) {
    __shared__ float sjs[SEH][16];
    int tid = threadIdx.x;
    int n0 = blockIdx.x * 16;
    int bb = n0 / HW;
    int hw0 = n0 % HW;

    int j = tid >> 4, nn = tid & 15;
    sjs[j][nn] = g_s[(size_t)bb * SEH * HW + (size_t)j * HW + hw0 + nn] * g_g[bb * SEH + j];
    __syncthreads();

    int o = tid;
    float wreg[SEH];
#pragma unroll
    for (int jj = 0; jj < SEH; jj++) wreg[jj] = Wout[o * SEH + jj];
    float scl = gout[o] * rsqrtf(vout[o] + EPS);
    float bo = bout[o] - mout[o] * scl;
    float* op = out + (size_t)bb * CO * HW + (size_t)o * HW + hw0;
#pragma unroll
    for (int nq = 0; nq < 4; nq++) {
        float4 a = make_float4(0.f, 0.f, 0.f, 0.f);
#pragma unroll
        for (int jj = 0; jj < SEH; jj++) {
            float wv = wreg[jj];
            a.x += wv * sjs[jj][nq * 4 + 0];
            a.y += wv * sjs[jj][nq * 4 + 1];
            a.z += wv * sjs[jj][nq * 4 + 2];
            a.w += wv * sjs[jj][nq * 4 + 3];
        }
        float4 r;
        r.x = a.x * scl + bo; r.y = a.y * scl + bo;
        r.z = a.z * scl + bo; r.w = a.w * scl + bo;
        *(float4*)&op[nq * 4] = r;
    }
}

// ---------------- launch ----------------
extern "C" void kernel_launch(void* const* d_in, const int* in_sizes, int n_in,
                              void* d_out, int out_size) {
    const float* x       = (const float*)d_in[0];
    const float* Wq      = (const float*)d_in[1];
    const float* Wk      = (const float*)d_in[2];
    const float* Wv      = (const float*)d_in[3];
    const float* rel_h   = (const float*)d_in[4];
    const float* rel_w   = (const float*)d_in[5];
    const float* agg_g1  = (const float*)d_in[6];
    const float* agg_b1  = (const float*)d_in[7];
    const float* agg_m1  = (const float*)d_in[8];
    const float* agg_v1  = (const float*)d_in[9];
    const float* agg_W   = (const float*)d_in[10];
    const float* agg_g2  = (const float*)d_in[11];
    const float* agg_b2  = (const float*)d_in[12];
    const float* agg_m2  = (const float*)d_in[13];
    const float* agg_v2  = (const float*)d_in[14];
    const float* se_Win  = (const float*)d_in[15];
    const float* se_g_in = (const float*)d_in[16];
    const float* se_b_in = (const float*)d_in[17];
    const float* se_m_in = (const float*)d_in[18];
    const float* se_v_in = (const float*)d_in[19];
    const float* se_fc1  = (const float*)d_in[20];
    const float* se_fc2  = (const float*)d_in[21];
    const float* se_Wout = (const float*)d_in[22];
    const float* se_g_out= (const float*)d_in[23];
    const float* se_b_out= (const float*)d_in[24];
    const float* se_m_out= (const float*)d_in[25];
    const float* se_v_out= (const float*)d_in[26];
    float* out = (float*)d_out;

    repack_w_kernel<<<1024, 256>>>(Wq, Wk, Wv, agg_W);
    transpose_x_kernel<<<dim3(98, 8, 4), dim3(32, 8)>>>(x);

    gemm_mma_kernel<<<dim3(98, 2, 3), 256>>>(nullptr, nullptr, nullptr, nullptr, 0);

    attn_kernel<<<dim3(196, NHEAD, NB), 256>>>(rel_h, rel_w, agg_g1, agg_b1, agg_m1, agg_v1);

    gemm_mma_kernel<<<dim3(98, 2, 1), 256>>>(agg_g2, agg_b2, agg_m2, agg_v2, 1);

    zero_p_kernel<<<1, 64>>>();
    se1_kernel<<<NCOL / 64, 256>>>(se_Win, se_g_in, se_b_in, se_m_in, se_v_in);
    se2_kernel<<<1, 64>>>(se_fc1, se_fc2);
    se3_kernel<<<NCOL / 16, 256>>>(se_Wout, se_g_out, se_b_out, se_m_out, se_v_out, out);
}

// round 12
// speedup vs baseline: 1.6658x; 1.1998x over previous
#include <cuda_runtime.h>
#include <math.h>
#include <stdint.h>

#define NB 4
#define CIN 256
#define CO 256
#define HDIM 56
#define WDIM 56
#define HW 3136
#define NCOL 12544     // NB*HW
#define NHEAD 2
#define HD 128
#define EPS 1e-5f
#define SEH 16
#define NPAN 98        // NCOL/128
#define CHUNKW 2048    // u32 per 128x16 chunk image

// attention dynamic smem layout (floats)
#define KV_STRIDE 132
#define KV_ROWS 72
#define QB_OFF   (KV_ROWS * KV_STRIDE)          // 9504
#define AW_STRIDE 68
#define SS_OFF   (QB_OFF + 16 * KV_STRIDE)      // 11616
#define SS_STRIDE 76
#define SMEM_ATTN ((SS_OFF + 16 * SS_STRIDE) * 4)   // 51328 bytes

// ---------------- scratch (device globals, no allocation) ----------------
__device__ uint32_t g_Wp [4 * 2 * 16 * CHUNKW];   // weight A-panels (tf32 frag layout)
__device__ uint32_t g_xtp[NPAN * 16 * CHUNKW];    // x B-panels
__device__ uint32_t g_y1p[NPAN * 16 * CHUNKW];    // y1 B-panels
__device__ float g_qt[NCOL * CO];   // [n][c]
__device__ float g_kt[NCOL * CO];
__device__ float g_vt[NCOL * CO];
__device__ float g_y2[NCOL * CO];   // agg out + BN2, [n][c]
__device__ float g_s [NB * SEH * HW]; // channel-major [b][j][hw]
__device__ float g_p [NB * SEH];
__device__ float g_g [NB * SEH];

// ---------------- helpers ----------------
__device__ __forceinline__ uint32_t f2tf32(float f) {
    uint32_t u;
    asm("cvt.rna.tf32.f32 %0, %1;" : "=r"(u) : "f"(f));
    return u;
}
__device__ __forceinline__ void cpasync16(uint32_t smem, const void* g) {
    asm volatile("cp.async.cg.shared.global [%0], [%1], 16;" :: "r"(smem), "l"(g));
}
__device__ __forceinline__ uint32_t smem_u32x(const void* p) {
    uint32_t a;
    asm("{ .reg .u64 t; cvta.to.shared.u64 t, %1; cvt.u32.u64 %0, t; }" : "=r"(a) : "l"(p));
    return a;
}
__device__ __forceinline__ void mma_tf32(float* d, const uint32_t* a, const uint32_t* b) {
    asm volatile(
        "mma.sync.aligned.m16n8k8.row.col.f32.tf32.tf32.f32 "
        "{%0,%1,%2,%3}, {%4,%5,%6,%7}, {%8,%9}, {%0,%1,%2,%3};"
        : "+f"(d[0]), "+f"(d[1]), "+f"(d[2]), "+f"(d[3])
        : "r"(a[0]), "r"(a[1]), "r"(a[2]), "r"(a[3]), "r"(b[0]), "r"(b[1]));
}

// A-image u32 offset within one 128x16 chunk (m rows x k cols)
__device__ __forceinline__ int a_off(int m, int k) {
    int ks = k >> 3, mtile = m >> 4, mi = m & 15;
    int lane = (mi & 7) * 4 + (k & 3);
    int slot = (mi >> 3) + 2 * ((k >> 2) & 1);
    int I = (ks * 8 + mtile) * 32 + lane;
    I ^= (I >> 3) & 3;
    return I * 4 + slot;
}
// B-image u32 offset within one 128x16 chunk (n rows x k cols)
__device__ __forceinline__ int b_off(int n, int k) {
    int ks = k >> 3, ntile = n >> 3;
    int lane = (n & 7) * 4 + (k & 3);
    int slot = (k >> 2) & 1;
    int I = (ks * 16 + ntile) * 32 + lane;
    I ^= (I >> 4) & 3;
    return I * 2 + slot;
}

// ---------------- weight repack: 4 matrices -> A-panels ----------------
__global__ void repack_w_kernel(const float* __restrict__ Wq, const float* __restrict__ Wk,
                                const float* __restrict__ Wv, const float* __restrict__ Wa) {
    int v = blockIdx.x * 256 + threadIdx.x;    // 4*256*256 values
    int mat = v >> 16;
    int rem = v & 65535;
    int o = rem >> 8, c = rem & 255;
    const float* W = (mat == 0) ? Wq : (mat == 1 ? Wk : (mat == 2 ? Wv : Wa));
    uint32_t u = f2tf32(W[o * 256 + c]);
    g_Wp[(((size_t)mat * 2 + (o >> 7)) * 16 + (c >> 4)) * CHUNKW + a_off(o & 127, c & 15)] = u;
}

// ---------------- transpose x: [b][c][hw] -> B-panels ----------------
__global__ void transpose_x_kernel(const float* __restrict__ x) {
    __shared__ float t[32][33];
    int b = blockIdx.z;
    int c0 = blockIdx.y * 32, p0 = blockIdx.x * 32;
    int tx = threadIdx.x, ty = threadIdx.y;   // 32 x 8
    const float* xb = x + ((size_t)b * CIN + c0) * HW + p0;
#pragma unroll
    for (int i = 0; i < 4; i++)
        t[ty * 4 + i][tx] = xb[(size_t)(ty * 4 + i) * HW + tx];
    __syncthreads();
    int c = c0 + tx;
#pragma unroll
    for (int i = 0; i < 4; i++) {
        int nglob = b * HW + p0 + ty * 4 + i;
        int ntile = nglob >> 7, nn = nglob & 127;
        g_xtp[((size_t)ntile * 16 + (c >> 4)) * CHUNKW + b_off(nn, c & 15)]
            = f2tf32(t[tx][ty * 4 + i]);
    }
}

// ---------------- tensor-core tf32 GEMM, cp.async 3-stage, M128 x N128 -----
__global__ __launch_bounds__(256, 2) void gemm_mma_kernel(
    const float* __restrict__ g2, const float* __restrict__ b2,
    const float* __restrict__ m2, const float* __restrict__ v2,
    int mode)
{
    __shared__ __align__(16) char smraw[49152];
    float* stg = (float*)smraw;

    int tid = threadIdx.x;
    int wid = tid >> 5, lane = tid & 31;
    int warpM = wid >> 2, warpN = wid & 3;
    int g = lane >> 2, t = lane & 3;

    int mat;
    const uint32_t* Bbase;
    float* outp;
    if (mode == 0) {
        mat = blockIdx.z;
        Bbase = g_xtp;
        outp = (mat == 0) ? g_qt : (mat == 1 ? g_kt : g_vt);
    } else {
        mat = 3; Bbase = g_y1p; outp = g_y2;
    }
    int o0 = blockIdx.y * 128;
    int n0 = blockIdx.x * 128;

    const uint4* Apan = (const uint4*)&g_Wp[((size_t)mat * 2 + blockIdx.y) * 16 * CHUNKW];
    const uint4* Bpan = (const uint4*)&Bbase[(size_t)blockIdx.x * 16 * CHUNKW];
    uint32_t smb = smem_u32x(smraw);

    float acc[4][4][4];
#pragma unroll
    for (int i = 0; i < 4; i++)
#pragma unroll
        for (int j = 0; j < 4; j++)
#pragma unroll
            for (int s = 0; s < 4; s++) acc[i][j][s] = 0.f;

#define ISSUE(c, s) do { \
        uint32_t dst = smb + (s) * 16384; \
        const uint4* sa = Apan + (c) * 512; \
        const uint4* sb = Bpan + (c) * 512; \
        cpasync16(dst + tid * 16,                sa + tid); \
        cpasync16(dst + (tid + 256) * 16,        sa + tid + 256); \
        cpasync16(dst + 8192 + tid * 16,         sb + tid); \
        cpasync16(dst + 8192 + (tid + 256) * 16, sb + tid + 256); \
        asm volatile("cp.async.commit_group;"); \
    } while (0)

    ISSUE(0, 0);
    ISSUE(1, 1);

    for (int c = 0; c < 16; c++) {
        if (c < 15) asm volatile("cp.async.wait_group 1;");
        else        asm volatile("cp.async.wait_group 0;");
        __syncthreads();
        if (c + 2 < 16) ISSUE(c + 2, (c + 2) % 3);

        const uint4* Ab = (const uint4*)(smraw + (c % 3) * 16384);
        const uint2* Bb = (const uint2*)(smraw + (c % 3) * 16384 + 8192);
#pragma unroll
        for (int ks = 0; ks < 2; ks++) {
            uint32_t af[4][4], bf[4][2];
#pragma unroll
            for (int mt = 0; mt < 4; mt++) {
                int idx = (ks * 8 + warpM * 4 + mt) * 32 + lane;
                idx ^= (idx >> 3) & 3;
                uint4 v = Ab[idx];
                af[mt][0] = v.x; af[mt][1] = v.y; af[mt][2] = v.z; af[mt][3] = v.w;
            }
#pragma unroll
            for (int nt = 0; nt < 4; nt++) {
                int idx = (ks * 16 + warpN * 4 + nt) * 32 + lane;
                idx ^= (idx >> 4) & 3;
                uint2 v = Bb[idx];
                bf[nt][0] = v.x; bf[nt][1] = v.y;
            }
#pragma unroll
            for (int mt = 0; mt < 4; mt++)
#pragma unroll
                for (int nt = 0; nt < 4; nt++)
                    mma_tf32(acc[mt][nt], af[mt], bf[nt]);
        }
        __syncthreads();
    }
#undef ISSUE

    int h_of_warp = warpN >> 1;
    for (int h = 0; h < 2; h++) {
        __syncthreads();
        if (h_of_warp == h) {
#pragma unroll
            for (int mt = 0; mt < 4; mt++)
#pragma unroll
                for (int nt = 0; nt < 4; nt++)
#pragma unroll
                    for (int s = 0; s < 4; s++) {
                        int ol = warpM * 64 + mt * 16 + g + (s >> 1) * 8;
                        int nl = (warpN & 1) * 32 + nt * 8 + 2 * t + (s & 1);
                        stg[nl * 132 + ol] = acc[mt][nt][s];
                    }
        }
        __syncthreads();
#pragma unroll
        for (int i = 0; i < 8; i++) {
            int idx = tid + 256 * i;
            int nl = idx >> 5, o4 = idx & 31;
            float4 v = *(float4*)&stg[nl * 132 + o4 * 4];
            if (mode == 1) {
                int ob = o0 + o4 * 4;
                float4 gg = *(const float4*)&g2[ob];
                float4 bb = *(const float4*)&b2[ob];
                float4 mm = *(const float4*)&m2[ob];
                float4 vv = *(const float4*)&v2[ob];
                float s0 = gg.x * rsqrtf(vv.x + EPS);
                float s1 = gg.y * rsqrtf(vv.y + EPS);
                float s2 = gg.z * rsqrtf(vv.z + EPS);
                float s3 = gg.w * rsqrtf(vv.w + EPS);
                v.x = v.x * s0 + (bb.x - mm.x * s0);
                v.y = v.y * s1 + (bb.y - mm.y * s1);
                v.z = v.z * s2 + (bb.z - mm.z * s2);
                v.w = v.w * s3 + (bb.w - mm.w * s3);
            }
            *(float4*)&outp[(size_t)(n0 + h * 64 + nl) * 256 + o0 + o4 * 4] = v;
        }
    }
}

// ---------------- attention: tensor-core (mma.sync tf32) --------------------
// CTA per (b, head, 4x4 pixel tile).  Halo K (8x8) + 5 rel-tap rows form a
// 72-row K'; scores = Q.K'^T via mma (bias taps come out of the same GEMM).
// Softmax builds a dense zero-filled 16x64 weight matrix; AV via mma.
// OOB halo rows are zero => score 0 + bias, matching reference zero-pad.
__global__ void attn_kernel(const float* __restrict__ rel_h,
                            const float* __restrict__ rel_w,
                            const float* __restrict__ g1, const float* __restrict__ b1,
                            const float* __restrict__ m1, const float* __restrict__ v1) {
    extern __shared__ float sm[];
    float* kv = sm;              // [72][132]  K' then V
    float* qb = sm + QB_OFF;     // [16][132]  Q, later attnw[16][68]
    float* sS = sm + SS_OFF;     // [16][76]   scores, later scl[128]/bo[128]

    int tid = threadIdx.x, wid = tid >> 5, lane = tid & 31;
    int g = lane >> 2, t4 = lane & 3;
    int tile = blockIdx.x;
    int th = tile / 14, tw = tile % 14;
    int nh = blockIdx.y, b = blockIdx.z;
    int h0 = th * 4, w0 = tw * 4;
    const float* rel = nh ? rel_w : rel_h;

    // ---- load Q (tf32-rounded) ----
    const float* qbase = g_qt + (size_t)b * HW * CO + nh * HD;
#pragma unroll
    for (int i = 0; i < 2; i++) {
        int f = tid + 256 * i;
        int m = f >> 5, c4 = f & 31;
        int hw = (h0 + (m >> 2)) * WDIM + w0 + (m & 3);
        float4 v = *(const float4*)&qbase[(size_t)hw * CO + c4 * 4];
        qb[m * KV_STRIDE + c4 * 4 + 0] = __uint_as_float(f2tf32(v.x));
        qb[m * KV_STRIDE + c4 * 4 + 1] = __uint_as_float(f2tf32(v.y));
        qb[m * KV_STRIDE + c4 * 4 + 2] = __uint_as_float(f2tf32(v.z));
        qb[m * KV_STRIDE + c4 * 4 + 3] = __uint_as_float(f2tf32(v.w));
    }
    // ---- load K halo ----
    const float* kbase = g_kt + (size_t)b * HW * CO + nh * HD;
#pragma unroll
    for (int i = 0; i < 8; i++) {
        int f = tid + 256 * i;
        int pos = f >> 5, c4 = f & 31;
        int hh = h0 - 2 + (pos >> 3), ww = w0 - 2 + (pos & 7);
        float4 v = make_float4(0.f, 0.f, 0.f, 0.f);
        if ((unsigned)hh < HDIM && (unsigned)ww < WDIM)
            v = *(const float4*)&kbase[(size_t)(hh * WDIM + ww) * CO + c4 * 4];
        kv[pos * KV_STRIDE + c4 * 4 + 0] = __uint_as_float(f2tf32(v.x));
        kv[pos * KV_STRIDE + c4 * 4 + 1] = __uint_as_float(f2tf32(v.y));
        kv[pos * KV_STRIDE + c4 * 4 + 2] = __uint_as_float(f2tf32(v.z));
        kv[pos * KV_STRIDE + c4 * 4 + 3] = __uint_as_float(f2tf32(v.w));
    }
    // ---- rel rows 64..68, zeros 69..71 ----
    {
        int pos = 64 + (tid >> 5), c4 = tid & 31;
        float vl[4] = {0.f, 0.f, 0.f, 0.f};
        if (pos < 69) {
            int tp = pos - 64;
#pragma unroll
            for (int j = 0; j < 4; j++) vl[j] = rel[(c4 * 4 + j) * 5 + tp];
        }
#pragma unroll
        for (int j = 0; j < 4; j++)
            kv[pos * KV_STRIDE + c4 * 4 + j] = __uint_as_float(f2tf32(vl[j]));
    }
    __syncthreads();

    // ---- scores mma: warp w does n-tile w; warp 0 also tile 8 (bias) ----
    float accS0[4] = {0.f, 0.f, 0.f, 0.f};
    float accS1[4] = {0.f, 0.f, 0.f, 0.f};
#pragma unroll
    for (int ks = 0; ks < 16; ks++) {
        int kk = ks * 8 + t4;
        uint32_t a[4];
        a[0] = __float_as_uint(qb[g * KV_STRIDE + kk]);
        a[1] = __float_as_uint(qb[(g + 8) * KV_STRIDE + kk]);
        a[2] = __float_as_uint(qb[g * KV_STRIDE + kk + 4]);
        a[3] = __float_as_uint(qb[(g + 8) * KV_STRIDE + kk + 4]);
        uint32_t bb[2];
        bb[0] = __float_as_uint(kv[(wid * 8 + g) * KV_STRIDE + kk]);
        bb[1] = __float_as_uint(kv[(wid * 8 + g) * KV_STRIDE + kk + 4]);
        mma_tf32(accS0, a, bb);
        if (wid == 0) {
            uint32_t b2r[2];
            b2r[0] = __float_as_uint(kv[(64 + g) * KV_STRIDE + kk]);
            b2r[1] = __float_as_uint(kv[(64 + g) * KV_STRIDE + kk + 4]);
            mma_tf32(accS1, a, b2r);
        }
    }
#pragma unroll
    for (int s = 0; s < 4; s++) {
        int m = g + (s >> 1) * 8;
        sS[m * SS_STRIDE + wid * 8 + 2 * t4 + (s & 1)] = accS0[s];
        if (wid == 0) sS[m * SS_STRIDE + 64 + 2 * t4 + (s & 1)] = accS1[s];
    }
    __syncthreads();

    // ---- load V over kv rows 0..63 ----
    const float* vbase = g_vt + (size_t)b * HW * CO + nh * HD;
#pragma unroll
    for (int i = 0; i < 8; i++) {
        int f = tid + 256 * i;
        int pos = f >> 5, c4 = f & 31;
        int hh = h0 - 2 + (pos >> 3), ww = w0 - 2 + (pos & 7);
        float4 v = make_float4(0.f, 0.f, 0.f, 0.f);
        if ((unsigned)hh < HDIM && (unsigned)ww < WDIM)
            v = *(const float4*)&vbase[(size_t)(hh * WDIM + ww) * CO + c4 * 4];
        kv[pos * KV_STRIDE + c4 * 4 + 0] = __uint_as_float(f2tf32(v.x));
        kv[pos * KV_STRIDE + c4 * 4 + 1] = __uint_as_float(f2tf32(v.y));
        kv[pos * KV_STRIDE + c4 * 4 + 2] = __uint_as_float(f2tf32(v.z));
        kv[pos * KV_STRIDE + c4 * 4 + 3] = __uint_as_float(f2tf32(v.w));
    }

    // ---- softmax: warp w handles pixels 2w, 2w+1; writes dense attnw ----
#pragma unroll
    for (int pp = 0; pp < 2; pp++) {
        int pi = wid * 2 + pp;
        int py = pi >> 2, px = pi & 3;
        float scv = -1e30f;
        int pos = 0;
        if (lane < 25) {
            int ki = lane / 5, kj = lane % 5;
            pos = (py + ki) * 8 + (px + kj);
            float bias = sS[pi * SS_STRIDE + 64 + (nh ? kj : ki)];
            scv = (sS[pi * SS_STRIDE + pos] + bias) * 0.08838834764831845f;
        }
        float mx = scv;
#pragma unroll
        for (int m = 16; m; m >>= 1) mx = fmaxf(mx, __shfl_xor_sync(0xffffffffu, mx, m));
        float e = (lane < 25) ? __expf(scv - mx) : 0.f;
        float ssum = e;
#pragma unroll
        for (int m = 16; m; m >>= 1) ssum += __shfl_xor_sync(0xffffffffu, ssum, m);
        float wv = e / ssum;
        float* aw = qb;                    // reuse q region
        aw[pi * AW_STRIDE + lane] = 0.f;
        aw[pi * AW_STRIDE + 32 + lane] = 0.f;
        if (lane < 25) aw[pi * AW_STRIDE + pos] = __uint_as_float(f2tf32(wv));
    }
    __syncthreads();

    // ---- BN1 scale/bias into sS (scores dead) ----
    if (tid < 128) {
        int ch = nh * HD + tid;
        float scl = g1[ch] * rsqrtf(v1[ch] + EPS);
        sS[tid] = scl;
        sS[128 + tid] = b1[ch] - m1[ch] * scl;
    }

    // ---- AV mma: warp w -> channel n-tiles 2w, 2w+1 ----
    float accV0[4] = {0.f, 0.f, 0.f, 0.f};
    float accV1[4] = {0.f, 0.f, 0.f, 0.f};
#pragma unroll
    for (int ks = 0; ks < 8; ks++) {
        int kk = ks * 8 + t4;
        uint32_t a[4];
        a[0] = __float_as_uint(qb[g * AW_STRIDE + kk]);
        a[1] = __float_as_uint(qb[(g + 8) * AW_STRIDE + kk]);
        a[2] = __float_as_uint(qb[g * AW_STRIDE + kk + 4]);
        a[3] = __float_as_uint(qb[(g + 8) * AW_STRIDE + kk + 4]);
        uint32_t bb[2];
        int c0 = wid * 16 + g;
        bb[0] = __float_as_uint(kv[kk * KV_STRIDE + c0]);
        bb[1] = __float_as_uint(kv[(kk + 4) * KV_STRIDE + c0]);
        mma_tf32(accV0, a, bb);
        bb[0] = __float_as_uint(kv[kk * KV_STRIDE + c0 + 8]);
        bb[1] = __float_as_uint(kv[(kk + 4) * KV_STRIDE + c0 + 8]);
        mma_tf32(accV1, a, bb);
    }
    __syncthreads();   // scl/bo visible

    // ---- epilogue: BN1 + relu -> g_y1p panels ----
#pragma unroll
    for (int j = 0; j < 2; j++) {
        const float* acc = j ? accV1 : accV0;
        int ntc = wid * 2 + j;
#pragma unroll
        for (int s = 0; s < 4; s++) {
            int m = g + (s >> 1) * 8;
            int c = ntc * 8 + 2 * t4 + (s & 1);
            int ch = nh * HD + c;
            int hw = (h0 + (m >> 2)) * WDIM + w0 + (m & 3);
            int nglob = b * HW + hw;
            float val = fmaxf(acc[s] * sS[c] + sS[128 + c], 0.f);
            g_y1p[((size_t)(nglob >> 7) * 16 + (ch >> 4)) * CHUNKW + b_off(nglob & 127, ch & 15)]
                = f2tf32(val);
        }
    }
}

// ---------------- zero p accumulator ----------------
__global__ void zero_p_kernel() {
    if (threadIdx.x < NB * SEH) g_p[threadIdx.x] = 0.f;
}

// ---------------- SE stage 1 ----------------
__global__ __launch_bounds__(256) void se1_kernel(const float* __restrict__ Win,
                           const float* __restrict__ gin, const float* __restrict__ bin,
                           const float* __restrict__ min_, const float* __restrict__ vin) {
    __shared__ float Ws[SEH * CO];
    __shared__ float pool[SEH];
    int tid = threadIdx.x, wid = tid >> 5, lane = tid & 31;
    for (int i = tid; i < SEH * CO; i += 256) Ws[i] = Win[i];
    if (tid < SEH) pool[tid] = 0.f;
    __syncthreads();

    int n0 = blockIdx.x * 64;
    int bb = n0 / HW;
    int hwb = n0 % HW;

    float scl = 0.f, bo = 0.f;
    if (lane < SEH) {
        scl = gin[lane] * rsqrtf(vin[lane] + EPS);
        bo = bin[lane] - min_[lane] * scl;
    }

    for (int px = wid; px < 64; px += 8) {
        const float* y = &g_y2[(size_t)(n0 + px) * CO];
        float4 v0 = *(const float4*)&y[lane * 4];
        float4 v1 = *(const float4*)&y[128 + lane * 4];
        float sj_me = 0.f;
#pragma unroll
        for (int j = 0; j < SEH; j++) {
            const float* wj = &Ws[j * CO];
            float4 w0 = *(const float4*)&wj[lane * 4];
            float4 w1 = *(const float4*)&wj[128 + lane * 4];
            float p = v0.x * w0.x + v0.y * w0.y + v0.z * w0.z + v0.w * w0.w
                    + v1.x * w1.x + v1.y * w1.y + v1.z * w1.z + v1.w * w1.w;
#pragma unroll
            for (int m = 16; m; m >>= 1) p += __shfl_xor_sync(0xffffffffu, p, m);
            if (lane == j) sj_me = p;
        }
        if (lane < SEH) {
            float sv = fmaxf(sj_me * scl + bo, 0.f);
            g_s[(size_t)bb * SEH * HW + (size_t)lane * HW + (hwb + px)] = sv;
            atomicAdd(&pool[lane], sv);
        }
    }
    __syncthreads();
    if (tid < SEH) atomicAdd(&g_p[bb * SEH + tid], pool[tid]);
}

// ---------------- SE stage 2 ----------------
__global__ void se2_kernel(const float* __restrict__ fc1, const float* __restrict__ fc2) {
    int tid = threadIdx.x;
    if (tid < NB * SEH) {
        int bb = tid >> 4, i = tid & 15;
        float hsum = 0.f;
#pragma unroll
        for (int j = 0; j < SEH; j++) hsum += (g_p[bb * SEH + j] * (1.f / HW)) * fc1[j];
        float hid = fmaxf(hsum, 0.f);
        g_g[tid] = 1.f / (1.f + __expf(-(hid * fc2[i])));
    }
}

// ---------------- SE stage 3 ----------------
__global__ void se3_kernel(const float* __restrict__ Wout,
                           const float* __restrict__ gout, const float* __restrict__ bout,
                           const float* __restrict__ mout, const float* __restrict__ vout,
                           float* __restrict__ out) {
    __shared__ float sjs[SEH][16];
    int tid = threadIdx.x;
    int n0 = blockIdx.x * 16;
    int bb = n0 / HW;
    int hw0 = n0 % HW;

    int j = tid >> 4, nn = tid & 15;
    sjs[j][nn] = g_s[(size_t)bb * SEH * HW + (size_t)j * HW + hw0 + nn] * g_g[bb * SEH + j];
    __syncthreads();

    int o = tid;
    float wreg[SEH];
#pragma unroll
    for (int jj = 0; jj < SEH; jj++) wreg[jj] = Wout[o * SEH + jj];
    float scl = gout[o] * rsqrtf(vout[o] + EPS);
    float bo = bout[o] - mout[o] * scl;
    float* op = out + (size_t)bb * CO * HW + (size_t)o * HW + hw0;
#pragma unroll
    for (int nq = 0; nq < 4; nq++) {
        float4 a = make_float4(0.f, 0.f, 0.f, 0.f);
#pragma unroll
        for (int jj = 0; jj < SEH; jj++) {
            float wv = wreg[jj];
            a.x += wv * sjs[jj][nq * 4 + 0];
            a.y += wv * sjs[jj][nq * 4 + 1];
            a.z += wv * sjs[jj][nq * 4 + 2];
            a.w += wv * sjs[jj][nq * 4 + 3];
        }
        float4 r;
        r.x = a.x * scl + bo; r.y = a.y * scl + bo;
        r.z = a.z * scl + bo; r.w = a.w * scl + bo;
        *(float4*)&op[nq * 4] = r;
    }
}

// ---------------- launch ----------------
extern "C" void kernel_launch(void* const* d_in, const int* in_sizes, int n_in,
                              void* d_out, int out_size) {
    const float* x       = (const float*)d_in[0];
    const float* Wq      = (const float*)d_in[1];
    const float* Wk      = (const float*)d_in[2];
    const float* Wv      = (const float*)d_in[3];
    const float* rel_h   = (const float*)d_in[4];
    const float* rel_w   = (const float*)d_in[5];
    const float* agg_g1  = (const float*)d_in[6];
    const float* agg_b1  = (const float*)d_in[7];
    const float* agg_m1  = (const float*)d_in[8];
    const float* agg_v1  = (const float*)d_in[9];
    const float* agg_W   = (const float*)d_in[10];
    const float* agg_g2  = (const float*)d_in[11];
    const float* agg_b2  = (const float*)d_in[12];
    const float* agg_m2  = (const float*)d_in[13];
    const float* agg_v2  = (const float*)d_in[14];
    const float* se_Win  = (const float*)d_in[15];
    const float* se_g_in = (const float*)d_in[16];
    const float* se_b_in = (const float*)d_in[17];
    const float* se_m_in = (const float*)d_in[18];
    const float* se_v_in = (const float*)d_in[19];
    const float* se_fc1  = (const float*)d_in[20];
    const float* se_fc2  = (const float*)d_in[21];
    const float* se_Wout = (const float*)d_in[22];
    const float* se_g_out= (const float*)d_in[23];
    const float* se_b_out= (const float*)d_in[24];
    const float* se_m_out= (const float*)d_in[25];
    const float* se_v_out= (const float*)d_in[26];
    float* out = (float*)d_out;

    cudaFuncSetAttribute(attn_kernel,
                         cudaFuncAttributeMaxDynamicSharedMemorySize, SMEM_ATTN);

    repack_w_kernel<<<1024, 256>>>(Wq, Wk, Wv, agg_W);
    transpose_x_kernel<<<dim3(98, 8, 4), dim3(32, 8)>>>(x);

    gemm_mma_kernel<<<dim3(98, 2, 3), 256>>>(nullptr, nullptr, nullptr, nullptr, 0);

    attn_kernel<<<dim3(196, NHEAD, NB), 256, SMEM_ATTN>>>(rel_h, rel_w,
                                                          agg_g1, agg_b1, agg_m1, agg_v1);

    gemm_mma_kernel<<<dim3(98, 2, 1), 256>>>(agg_g2, agg_b2, agg_m2, agg_v2, 1);

    zero_p_kernel<<<1, 64>>>();
    se1_kernel<<<NCOL / 64, 256>>>(se_Win, se_g_in, se_b_in, se_m_in, se_v_in);
    se2_kernel<<<1, 64>>>(se_fc1, se_fc2);
    se3_kernel<<<NCOL / 16, 256>>>(se_Wout, se_g_out, se_b_out, se_m_out, se_v_out, out);
}

// round 13
// speedup vs baseline: 1.7803x; 1.0687x over previous
#include <cuda_runtime.h>
#include <math.h>
#include <stdint.h>

#define NB 4
#define CIN 256
#define CO 256
#define HDIM 56
#define WDIM 56
#define HW 3136
#define NCOL 12544     // NB*HW
#define NHEAD 2
#define HD 128
#define EPS 1e-5f
#define SEH 16
#define NPAN 98        // NCOL/128
#define CHUNKW 2048    // u32 per 128x16 chunk image

// attention dynamic smem layout (floats)
#define KV_STRIDE 132
#define KV_ROWS 72
#define QB_OFF   (KV_ROWS * KV_STRIDE)          // 9504
#define AW_STRIDE 68
#define SS_OFF   (QB_OFF + 16 * KV_STRIDE)      // 11616
#define SS_STRIDE 76
#define SMEM_ATTN ((SS_OFF + 16 * SS_STRIDE) * 4)   // 51328 bytes

// ---------------- scratch (device globals, no allocation) ----------------
__device__ uint32_t g_Wp [4 * 2 * 16 * CHUNKW];   // weight A-panels (tf32 frag layout)
__device__ uint32_t g_xtp[NPAN * 16 * CHUNKW];    // x B-panels
__device__ uint32_t g_y1p[NPAN * 16 * CHUNKW];    // y1 B-panels
__device__ uint32_t g_y2p[NPAN * 16 * CHUNKW];    // y2 B-panels
__device__ float g_qt[NCOL * CO];   // [n][c]
__device__ float g_kt[NCOL * CO];
__device__ float g_vt[NCOL * CO];
__device__ float g_s [NB * SEH * HW]; // channel-major [b][j][hw]
__device__ float g_p [NB * SEH];
__device__ float g_g [NB * SEH];

// ---------------- helpers ----------------
__device__ __forceinline__ uint32_t f2tf32(float f) {
    uint32_t u;
    asm("cvt.rna.tf32.f32 %0, %1;" : "=r"(u) : "f"(f));
    return u;
}
__device__ __forceinline__ float f2tf32f(float f) {
    return __uint_as_float(f2tf32(f));
}
__device__ __forceinline__ void cpasync16(uint32_t smem, const void* g) {
    asm volatile("cp.async.cg.shared.global [%0], [%1], 16;" :: "r"(smem), "l"(g));
}
__device__ __forceinline__ uint32_t smem_u32x(const void* p) {
    uint32_t a;
    asm("{ .reg .u64 t; cvta.to.shared.u64 t, %1; cvt.u32.u64 %0, t; }" : "=r"(a) : "l"(p));
    return a;
}
__device__ __forceinline__ void mma_tf32(float* d, const uint32_t* a, const uint32_t* b) {
    asm volatile(
        "mma.sync.aligned.m16n8k8.row.col.f32.tf32.tf32.f32 "
        "{%0,%1,%2,%3}, {%4,%5,%6,%7}, {%8,%9}, {%0,%1,%2,%3};"
        : "+f"(d[0]), "+f"(d[1]), "+f"(d[2]), "+f"(d[3])
        : "r"(a[0]), "r"(a[1]), "r"(a[2]), "r"(a[3]), "r"(b[0]), "r"(b[1]));
}

// A-image u32 offset within one 128x16 chunk (m rows x k cols)
__device__ __forceinline__ int a_off(int m, int k) {
    int ks = k >> 3, mtile = m >> 4, mi = m & 15;
    int lane = (mi & 7) * 4 + (k & 3);
    int slot = (mi >> 3) + 2 * ((k >> 2) & 1);
    int I = (ks * 8 + mtile) * 32 + lane;
    I ^= (I >> 3) & 3;
    return I * 4 + slot;
}
// B-image u32 offset within one 128x16 chunk (n rows x k cols)
__device__ __forceinline__ int b_off(int n, int k) {
    int ks = k >> 3, ntile = n >> 3;
    int lane = (n & 7) * 4 + (k & 3);
    int slot = (k >> 2) & 1;
    int I = (ks * 16 + ntile) * 32 + lane;
    I ^= (I >> 4) & 3;
    return I * 2 + slot;
}

// ---------------- weight repack: 4 matrices -> A-panels ----------------
__global__ void repack_w_kernel(const float* __restrict__ Wq, const float* __restrict__ Wk,
                                const float* __restrict__ Wv, const float* __restrict__ Wa) {
    int v = blockIdx.x * 256 + threadIdx.x;    // 4*256*256 values
    int mat = v >> 16;
    int rem = v & 65535;
    int o = rem >> 8, c = rem & 255;
    const float* W = (mat == 0) ? Wq : (mat == 1 ? Wk : (mat == 2 ? Wv : Wa));
    uint32_t u = f2tf32(W[o * 256 + c]);
    g_Wp[(((size_t)mat * 2 + (o >> 7)) * 16 + (c >> 4)) * CHUNKW + a_off(o & 127, c & 15)] = u;
}

// ---------------- transpose x: [b][c][hw] -> B-panels ----------------
__global__ void transpose_x_kernel(const float* __restrict__ x) {
    __shared__ float t[32][33];
    int b = blockIdx.z;
    int c0 = blockIdx.y * 32, p0 = blockIdx.x * 32;
    int tx = threadIdx.x, ty = threadIdx.y;   // 32 x 8
    const float* xb = x + ((size_t)b * CIN + c0) * HW + p0;
#pragma unroll
    for (int i = 0; i < 4; i++)
        t[ty * 4 + i][tx] = xb[(size_t)(ty * 4 + i) * HW + tx];
    __syncthreads();
    int c = c0 + tx;
#pragma unroll
    for (int i = 0; i < 4; i++) {
        int nglob = b * HW + p0 + ty * 4 + i;
        int ntile = nglob >> 7, nn = nglob & 127;
        g_xtp[((size_t)ntile * 16 + (c >> 4)) * CHUNKW + b_off(nn, c & 15)]
            = f2tf32(t[tx][ty * 4 + i]);
    }
}

// ---------------- tensor-core tf32 GEMM, cp.async 3-stage, M128 x N128 -----
// mode 0: qkv (z selects matrix 0..2, B=g_xtp, out flat [n][c])
// mode 1: agg (matrix 3, B=g_y1p, out g_y2p panels with BN2, tf32-rounded)
__global__ __launch_bounds__(256, 2) void gemm_mma_kernel(
    const float* __restrict__ g2, const float* __restrict__ b2,
    const float* __restrict__ m2, const float* __restrict__ v2,
    int mode)
{
    __shared__ __align__(16) char smraw[49152];
    float* stg = (float*)smraw;

    int tid = threadIdx.x;
    int wid = tid >> 5, lane = tid & 31;
    int warpM = wid >> 2, warpN = wid & 3;
    int g = lane >> 2, t = lane & 3;

    int mat;
    const uint32_t* Bbase;
    float* outp = nullptr;
    if (mode == 0) {
        mat = blockIdx.z;
        Bbase = g_xtp;
        outp = (mat == 0) ? g_qt : (mat == 1 ? g_kt : g_vt);
    } else {
        mat = 3; Bbase = g_y1p;
    }
    int o0 = blockIdx.y * 128;
    int n0 = blockIdx.x * 128;

    const uint4* Apan = (const uint4*)&g_Wp[((size_t)mat * 2 + blockIdx.y) * 16 * CHUNKW];
    const uint4* Bpan = (const uint4*)&Bbase[(size_t)blockIdx.x * 16 * CHUNKW];
    uint32_t smb = smem_u32x(smraw);

    float acc[4][4][4];
#pragma unroll
    for (int i = 0; i < 4; i++)
#pragma unroll
        for (int j = 0; j < 4; j++)
#pragma unroll
            for (int s = 0; s < 4; s++) acc[i][j][s] = 0.f;

#define ISSUE(c, s) do { \
        uint32_t dst = smb + (s) * 16384; \
        const uint4* sa = Apan + (c) * 512; \
        const uint4* sb = Bpan + (c) * 512; \
        cpasync16(dst + tid * 16,                sa + tid); \
        cpasync16(dst + (tid + 256) * 16,        sa + tid + 256); \
        cpasync16(dst + 8192 + tid * 16,         sb + tid); \
        cpasync16(dst + 8192 + (tid + 256) * 16, sb + tid + 256); \
        asm volatile("cp.async.commit_group;"); \
    } while (0)

    ISSUE(0, 0);
    ISSUE(1, 1);

    for (int c = 0; c < 16; c++) {
        if (c < 15) asm volatile("cp.async.wait_group 1;");
        else        asm volatile("cp.async.wait_group 0;");
        __syncthreads();
        if (c + 2 < 16) ISSUE(c + 2, (c + 2) % 3);

        const uint4* Ab = (const uint4*)(smraw + (c % 3) * 16384);
        const uint2* Bb = (const uint2*)(smraw + (c % 3) * 16384 + 8192);
#pragma unroll
        for (int ks = 0; ks < 2; ks++) {
            uint32_t af[4][4], bf[4][2];
#pragma unroll
            for (int mt = 0; mt < 4; mt++) {
                int idx = (ks * 8 + warpM * 4 + mt) * 32 + lane;
                idx ^= (idx >> 3) & 3;
                uint4 v = Ab[idx];
                af[mt][0] = v.x; af[mt][1] = v.y; af[mt][2] = v.z; af[mt][3] = v.w;
            }
#pragma unroll
            for (int nt = 0; nt < 4; nt++) {
                int idx = (ks * 16 + warpN * 4 + nt) * 32 + lane;
                idx ^= (idx >> 4) & 3;
                uint2 v = Bb[idx];
                bf[nt][0] = v.x; bf[nt][1] = v.y;
            }
#pragma unroll
            for (int mt = 0; mt < 4; mt++)
#pragma unroll
                for (int nt = 0; nt < 4; nt++)
                    mma_tf32(acc[mt][nt], af[mt], bf[nt]);
        }
        __syncthreads();
    }
#undef ISSUE

    int h_of_warp = warpN >> 1;
    for (int h = 0; h < 2; h++) {
        __syncthreads();
        if (h_of_warp == h) {
#pragma unroll
            for (int mt = 0; mt < 4; mt++)
#pragma unroll
                for (int nt = 0; nt < 4; nt++)
#pragma unroll
                    for (int s = 0; s < 4; s++) {
                        int ol = warpM * 64 + mt * 16 + g + (s >> 1) * 8;
                        int nl = (warpN & 1) * 32 + nt * 8 + 2 * t + (s & 1);
                        stg[nl * 132 + ol] = acc[mt][nt][s];
                    }
        }
        __syncthreads();
#pragma unroll
        for (int i = 0; i < 8; i++) {
            int idx = tid + 256 * i;
            int nl = idx >> 5, o4 = idx & 31;
            float4 v = *(float4*)&stg[nl * 132 + o4 * 4];
            int nglob = n0 + h * 64 + nl;
            if (mode == 1) {
                int ob = o0 + o4 * 4;
                float4 gg = *(const float4*)&g2[ob];
                float4 bb = *(const float4*)&b2[ob];
                float4 mm = *(const float4*)&m2[ob];
                float4 vv = *(const float4*)&v2[ob];
                float s0 = gg.x * rsqrtf(vv.x + EPS);
                float s1 = gg.y * rsqrtf(vv.y + EPS);
                float s2 = gg.z * rsqrtf(vv.z + EPS);
                float s3 = gg.w * rsqrtf(vv.w + EPS);
                v.x = v.x * s0 + (bb.x - mm.x * s0);
                v.y = v.y * s1 + (bb.y - mm.y * s1);
                v.z = v.z * s2 + (bb.z - mm.z * s2);
                v.w = v.w * s3 + (bb.w - mm.w * s3);
                // panel store (tf32) for SE1 mma consumption
                int pt = nglob >> 7, nn = nglob & 127;
                uint32_t* pb = &g_y2p[((size_t)pt * 16) * CHUNKW];
                const float* pv = &v.x;
#pragma unroll
                for (int j = 0; j < 4; j++) {
                    int ch = ob + j;
                    pb[(size_t)(ch >> 4) * CHUNKW + b_off(nn, ch & 15)] = f2tf32(pv[j]);
                }
            } else {
                *(float4*)&outp[(size_t)nglob * 256 + o0 + o4 * 4] = v;
            }
        }
    }
}

// ---------------- attention: tensor-core (mma.sync tf32) --------------------
__global__ void attn_kernel(const float* __restrict__ rel_h,
                            const float* __restrict__ rel_w,
                            const float* __restrict__ g1, const float* __restrict__ b1,
                            const float* __restrict__ m1, const float* __restrict__ v1) {
    extern __shared__ float sm[];
    float* kv = sm;              // [72][132]  K' then V
    float* qb = sm + QB_OFF;     // [16][132]  Q, later attnw[16][68]
    float* sS = sm + SS_OFF;     // [16][76]   scores, later scl[128]/bo[128]

    int tid = threadIdx.x, wid = tid >> 5, lane = tid & 31;
    int g = lane >> 2, t4 = lane & 3;
    int tile = blockIdx.x;
    int th = tile / 14, tw = tile % 14;
    int nh = blockIdx.y, b = blockIdx.z;
    int h0 = th * 4, w0 = tw * 4;
    const float* rel = nh ? rel_w : rel_h;

    // ---- load Q (tf32-rounded, vectorized) ----
    const float* qbase = g_qt + (size_t)b * HW * CO + nh * HD;
#pragma unroll
    for (int i = 0; i < 2; i++) {
        int f = tid + 256 * i;
        int m = f >> 5, c4 = f & 31;
        int hw = (h0 + (m >> 2)) * WDIM + w0 + (m & 3);
        float4 v = *(const float4*)&qbase[(size_t)hw * CO + c4 * 4];
        float4 r;
        r.x = f2tf32f(v.x); r.y = f2tf32f(v.y); r.z = f2tf32f(v.z); r.w = f2tf32f(v.w);
        *(float4*)&qb[m * KV_STRIDE + c4 * 4] = r;
    }
    // ---- load K halo ----
    const float* kbase = g_kt + (size_t)b * HW * CO + nh * HD;
#pragma unroll
    for (int i = 0; i < 8; i++) {
        int f = tid + 256 * i;
        int pos = f >> 5, c4 = f & 31;
        int hh = h0 - 2 + (pos >> 3), ww = w0 - 2 + (pos & 7);
        float4 v = make_float4(0.f, 0.f, 0.f, 0.f);
        if ((unsigned)hh < HDIM && (unsigned)ww < WDIM)
            v = *(const float4*)&kbase[(size_t)(hh * WDIM + ww) * CO + c4 * 4];
        float4 r;
        r.x = f2tf32f(v.x); r.y = f2tf32f(v.y); r.z = f2tf32f(v.z); r.w = f2tf32f(v.w);
        *(float4*)&kv[pos * KV_STRIDE + c4 * 4] = r;
    }
    // ---- rel rows 64..68, zeros 69..71 ----
    {
        int pos = 64 + (tid >> 5), c4 = tid & 31;
        float4 r = make_float4(0.f, 0.f, 0.f, 0.f);
        if (pos < 69) {
            int tp = pos - 64;
            r.x = f2tf32f(rel[(c4 * 4 + 0) * 5 + tp]);
            r.y = f2tf32f(rel[(c4 * 4 + 1) * 5 + tp]);
            r.z = f2tf32f(rel[(c4 * 4 + 2) * 5 + tp]);
            r.w = f2tf32f(rel[(c4 * 4 + 3) * 5 + tp]);
        }
        *(float4*)&kv[pos * KV_STRIDE + c4 * 4] = r;
    }
    __syncthreads();

    // ---- scores mma ----
    float accS0[4] = {0.f, 0.f, 0.f, 0.f};
    float accS1[4] = {0.f, 0.f, 0.f, 0.f};
#pragma unroll
    for (int ks = 0; ks < 16; ks++) {
        int kk = ks * 8 + t4;
        uint32_t a[4];
        a[0] = __float_as_uint(qb[g * KV_STRIDE + kk]);
        a[1] = __float_as_uint(qb[(g + 8) * KV_STRIDE + kk]);
        a[2] = __float_as_uint(qb[g * KV_STRIDE + kk + 4]);
        a[3] = __float_as_uint(qb[(g + 8) * KV_STRIDE + kk + 4]);
        uint32_t bb[2];
        bb[0] = __float_as_uint(kv[(wid * 8 + g) * KV_STRIDE + kk]);
        bb[1] = __float_as_uint(kv[(wid * 8 + g) * KV_STRIDE + kk + 4]);
        mma_tf32(accS0, a, bb);
        if (wid == 0) {
            uint32_t b2r[2];
            b2r[0] = __float_as_uint(kv[(64 + g) * KV_STRIDE + kk]);
            b2r[1] = __float_as_uint(kv[(64 + g) * KV_STRIDE + kk + 4]);
            mma_tf32(accS1, a, b2r);
        }
    }
#pragma unroll
    for (int s = 0; s < 4; s++) {
        int m = g + (s >> 1) * 8;
        sS[m * SS_STRIDE + wid * 8 + 2 * t4 + (s & 1)] = accS0[s];
        if (wid == 0) sS[m * SS_STRIDE + 64 + 2 * t4 + (s & 1)] = accS1[s];
    }
    __syncthreads();

    // ---- load V over kv rows 0..63 ----
    const float* vbase = g_vt + (size_t)b * HW * CO + nh * HD;
#pragma unroll
    for (int i = 0; i < 8; i++) {
        int f = tid + 256 * i;
        int pos = f >> 5, c4 = f & 31;
        int hh = h0 - 2 + (pos >> 3), ww = w0 - 2 + (pos & 7);
        float4 v = make_float4(0.f, 0.f, 0.f, 0.f);
        if ((unsigned)hh < HDIM && (unsigned)ww < WDIM)
            v = *(const float4*)&vbase[(size_t)(hh * WDIM + ww) * CO + c4 * 4];
        float4 r;
        r.x = f2tf32f(v.x); r.y = f2tf32f(v.y); r.z = f2tf32f(v.z); r.w = f2tf32f(v.w);
        *(float4*)&kv[pos * KV_STRIDE + c4 * 4] = r;
    }

    // ---- softmax: warp w handles pixels 2w, 2w+1; writes dense attnw ----
#pragma unroll
    for (int pp = 0; pp < 2; pp++) {
        int pi = wid * 2 + pp;
        int py = pi >> 2, px = pi & 3;
        float scv = -1e30f;
        int pos = 0;
        if (lane < 25) {
            int ki = lane / 5, kj = lane % 5;
            pos = (py + ki) * 8 + (px + kj);
            float bias = sS[pi * SS_STRIDE + 64 + (nh ? kj : ki)];
            scv = (sS[pi * SS_STRIDE + pos] + bias) * 0.08838834764831845f;
        }
        float mx = scv;
#pragma unroll
        for (int m = 16; m; m >>= 1) mx = fmaxf(mx, __shfl_xor_sync(0xffffffffu, mx, m));
        float e = (lane < 25) ? __expf(scv - mx) : 0.f;
        float ssum = e;
#pragma unroll
        for (int m = 16; m; m >>= 1) ssum += __shfl_xor_sync(0xffffffffu, ssum, m);
        float wv = e / ssum;
        float* aw = qb;
        aw[pi * AW_STRIDE + lane] = 0.f;
        aw[pi * AW_STRIDE + 32 + lane] = 0.f;
        if (lane < 25) aw[pi * AW_STRIDE + pos] = f2tf32f(wv);
    }
    __syncthreads();

    // ---- BN1 scale/bias into sS ----
    if (tid < 128) {
        int ch = nh * HD + tid;
        float scl = g1[ch] * rsqrtf(v1[ch] + EPS);
        sS[tid] = scl;
        sS[128 + tid] = b1[ch] - m1[ch] * scl;
    }

    // ---- AV mma ----
    float accV0[4] = {0.f, 0.f, 0.f, 0.f};
    float accV1[4] = {0.f, 0.f, 0.f, 0.f};
#pragma unroll
    for (int ks = 0; ks < 8; ks++) {
        int kk = ks * 8 + t4;
        uint32_t a[4];
        a[0] = __float_as_uint(qb[g * AW_STRIDE + kk]);
        a[1] = __float_as_uint(qb[(g + 8) * AW_STRIDE + kk]);
        a[2] = __float_as_uint(qb[g * AW_STRIDE + kk + 4]);
        a[3] = __float_as_uint(qb[(g + 8) * AW_STRIDE + kk + 4]);
        uint32_t bb[2];
        int c0 = wid * 16 + g;
        bb[0] = __float_as_uint(kv[kk * KV_STRIDE + c0]);
        bb[1] = __float_as_uint(kv[(kk + 4) * KV_STRIDE + c0]);
        mma_tf32(accV0, a, bb);
        bb[0] = __float_as_uint(kv[kk * KV_STRIDE + c0 + 8]);
        bb[1] = __float_as_uint(kv[(kk + 4) * KV_STRIDE + c0 + 8]);
        mma_tf32(accV1, a, bb);
    }
    __syncthreads();

    // ---- epilogue: BN1 + relu -> g_y1p panels ----
#pragma unroll
    for (int j = 0; j < 2; j++) {
        const float* acc = j ? accV1 : accV0;
        int ntc = wid * 2 + j;
#pragma unroll
        for (int s = 0; s < 4; s++) {
            int m = g + (s >> 1) * 8;
            int c = ntc * 8 + 2 * t4 + (s & 1);
            int ch = nh * HD + c;
            int hw = (h0 + (m >> 2)) * WDIM + w0 + (m & 3);
            int nglob = b * HW + hw;
            float val = fmaxf(acc[s] * sS[c] + sS[128 + c], 0.f);
            g_y1p[((size_t)(nglob >> 7) * 16 + (ch >> 4)) * CHUNKW + b_off(nglob & 127, ch & 15)]
                = f2tf32(val);
        }
    }
}

// ---------------- zero p accumulator ----------------
__global__ void zero_p_kernel() {
    if (threadIdx.x < NB * SEH) g_p[threadIdx.x] = 0.f;
}

// ---------------- SE stage 1: mma over y2 panels ----------------
// CTA per 128-pixel panel. A = Win fragments (m16), B = g_y2p fragments (LDG
// direct, coalesced). BN+relu epilogue -> g_s + pooled sums -> g_p.
__global__ __launch_bounds__(256) void se1_kernel(const float* __restrict__ Win,
                           const float* __restrict__ gin, const float* __restrict__ bin,
                           const float* __restrict__ min_, const float* __restrict__ vin) {
    __shared__ uint32_t Wf[4096];
    __shared__ float bnscl[SEH], bnbo[SEH];
    __shared__ float pool[2][SEH];
    int tid = threadIdx.x, wid = tid >> 5, lane = tid & 31;
    int g = lane >> 2, t4 = lane & 3;

    // build Win A-fragments (m16: mtile 0 only, no swizzle)
#pragma unroll
    for (int it = 0; it < 16; it++) {
        int i = tid + 256 * it;
        int m = i >> 8, k = i & 255;
        int kc = k >> 4, ks = (k >> 3) & 1;
        int laneA = (m & 7) * 4 + (k & 3);
        int slot = (m >> 3) + 2 * ((k >> 2) & 1);
        Wf[((kc * 2 + ks) * 32 + laneA) * 4 + slot] = f2tf32(Win[m * 256 + k]);
    }
    if (tid < SEH) {
        float scl = gin[tid] * rsqrtf(vin[tid] + EPS);
        bnscl[tid] = scl;
        bnbo[tid] = bin[tid] - min_[tid] * scl;
        pool[0][tid] = 0.f;
        pool[1][tid] = 0.f;
    }
    __syncthreads();

    int panel = blockIdx.x;
    const uint32_t* Bpan = g_y2p + (size_t)panel * 16 * CHUNKW;

    float acc[2][4];
#pragma unroll
    for (int nt = 0; nt < 2; nt++)
#pragma unroll
        for (int s = 0; s < 4; s++) acc[nt][s] = 0.f;

#pragma unroll
    for (int kc = 0; kc < 16; kc++) {
#pragma unroll
        for (int ks = 0; ks < 2; ks++) {
            uint4 av = ((const uint4*)Wf)[(kc * 2 + ks) * 32 + lane];
            uint32_t a[4] = {av.x, av.y, av.z, av.w};
#pragma unroll
            for (int nt = 0; nt < 2; nt++) {
                int ntile = wid * 2 + nt;
                int idx = (ks * 16 + ntile) * 32 + lane;
                idx ^= (idx >> 4) & 3;
                uint2 bv = *(const uint2*)(Bpan + (size_t)kc * CHUNKW + idx * 2);
                uint32_t bb[2] = {bv.x, bv.y};
                mma_tf32(acc[nt], a, bb);
            }
        }
    }

    int b_first = (panel * 128) / HW;
#pragma unroll
    for (int nt = 0; nt < 2; nt++) {
        int ntile = wid * 2 + nt;
#pragma unroll
        for (int s = 0; s < 4; s++) {
            int j = g + (s >> 1) * 8;
            int pix = ntile * 8 + 2 * t4 + (s & 1);
            int nglob = panel * 128 + pix;
            int b = nglob / HW, hw = nglob % HW;
            float sv = fmaxf(acc[nt][s] * bnscl[j] + bnbo[j], 0.f);
            g_s[(size_t)b * SEH * HW + (size_t)j * HW + hw] = sv;
            atomicAdd(&pool[b - b_first][j], sv);
        }
    }
    __syncthreads();
    if (tid < 2 * SEH) {
        int bl = tid >> 4, j = tid & 15;
        int b = b_first + bl;
        if (b < NB) atomicAdd(&g_p[b * SEH + j], pool[bl][j]);
    }
}

// ---------------- SE stage 2 ----------------
__global__ void se2_kernel(const float* __restrict__ fc1, const float* __restrict__ fc2) {
    int tid = threadIdx.x;
    if (tid < NB * SEH) {
        int bb = tid >> 4, i = tid & 15;
        float hsum = 0.f;
#pragma unroll
        for (int j = 0; j < SEH; j++) hsum += (g_p[bb * SEH + j] * (1.f / HW)) * fc1[j];
        float hid = fmaxf(hsum, 0.f);
        g_g[tid] = 1.f / (1.f + __expf(-(hid * fc2[i])));
    }
}

// ---------------- SE stage 3 ----------------
__global__ void se3_kernel(const float* __restrict__ Wout,
                           const float* __restrict__ gout, const float* __restrict__ bout,
                           const float* __restrict__ mout, const float* __restrict__ vout,
                           float* __restrict__ out) {
    __shared__ float sjs[SEH][16];
    int tid = threadIdx.x;
    int n0 = blockIdx.x * 16;
    int bb = n0 / HW;
    int hw0 = n0 % HW;

    int j = tid >> 4, nn = tid & 15;
    sjs[j][nn] = g_s[(size_t)bb * SEH * HW + (size_t)j * HW + hw0 + nn] * g_g[bb * SEH + j];
    __syncthreads();

    int o = tid;
    float wreg[SEH];
#pragma unroll
    for (int jj = 0; jj < SEH; jj++) wreg[jj] = Wout[o * SEH + jj];
    float scl = gout[o] * rsqrtf(vout[o] + EPS);
    float bo = bout[o] - mout[o] * scl;
    float* op = out + (size_t)bb * CO * HW + (size_t)o * HW + hw0;
#pragma unroll
    for (int nq = 0; nq < 4; nq++) {
        float4 a = make_float4(0.f, 0.f, 0.f, 0.f);
#pragma unroll
        for (int jj = 0; jj < SEH; jj++) {
            float wv = wreg[jj];
            a.x += wv * sjs[jj][nq * 4 + 0];
            a.y += wv * sjs[jj][nq * 4 + 1];
            a.z += wv * sjs[jj][nq * 4 + 2];
            a.w += wv * sjs[jj][nq * 4 + 3];
        }
        float4 r;
        r.x = a.x * scl + bo; r.y = a.y * scl + bo;
        r.z = a.z * scl + bo; r.w = a.w * scl + bo;
        *(float4*)&op[nq * 4] = r;
    }
}

// ---------------- launch ----------------
extern "C" void kernel_launch(void* const* d_in, const int* in_sizes, int n_in,
                              void* d_out, int out_size) {
    const float* x       = (const float*)d_in[0];
    const float* Wq      = (const float*)d_in[1];
    const float* Wk      = (const float*)d_in[2];
    const float* Wv      = (const float*)d_in[3];
    const float* rel_h   = (const float*)d_in[4];
    const float* rel_w   = (const float*)d_in[5];
    const float* agg_g1  = (const float*)d_in[6];
    const float* agg_b1  = (const float*)d_in[7];
    const float* agg_m1  = (const float*)d_in[8];
    const float* agg_v1  = (const float*)d_in[9];
    const float* agg_W   = (const float*)d_in[10];
    const float* agg_g2  = (const float*)d_in[11];
    const float* agg_b2  = (const float*)d_in[12];
    const float* agg_m2  = (const float*)d_in[13];
    const float* agg_v2  = (const float*)d_in[14];
    const float* se_Win  = (const float*)d_in[15];
    const float* se_g_in = (const float*)d_in[16];
    const float* se_b_in = (const float*)d_in[17];
    const float* se_m_in = (const float*)d_in[18];
    const float* se_v_in = (const float*)d_in[19];
    const float* se_fc1  = (const float*)d_in[20];
    const float* se_fc2  = (const float*)d_in[21];
    const float* se_Wout = (const float*)d_in[22];
    const float* se_g_out= (const float*)d_in[23];
    const float* se_b_out= (const float*)d_in[24];
    const float* se_m_out= (const float*)d_in[25];
    const float* se_v_out= (const float*)d_in[26];
    float* out = (float*)d_out;

    cudaFuncSetAttribute(attn_kernel,
                         cudaFuncAttributeMaxDynamicSharedMemorySize, SMEM_ATTN);

    repack_w_kernel<<<1024, 256>>>(Wq, Wk, Wv, agg_W);
    transpose_x_kernel<<<dim3(98, 8, 4), dim3(32, 8)>>>(x);

    gemm_mma_kernel<<<dim3(98, 2, 3), 256>>>(nullptr, nullptr, nullptr, nullptr, 0);

    attn_kernel<<<dim3(196, NHEAD, NB), 256, SMEM_ATTN>>>(rel_h, rel_w,
                                                          agg_g1, agg_b1, agg_m1, agg_v1);

    gemm_mma_kernel<<<dim3(98, 2, 1), 256>>>(agg_g2, agg_b2, agg_m2, agg_v2, 1);

    zero_p_kernel<<<1, 64>>>();
    se1_kernel<<<NPAN, 256>>>(se_Win, se_g_in, se_b_in, se_m_in, se_v_in);
    se2_kernel<<<1, 64>>>(se_fc1, se_fc2);
    se3_kernel<<<NCOL / 16, 256>>>(se_Wout, se_g_out, se_b_out, se_m_out, se_v_out, out);
}

// round 14
// speedup vs baseline: 1.8103x; 1.0169x over previous
#include <cuda_runtime.h>
#include <math.h>
#include <stdint.h>

#define NB 4
#define CIN 256
#define CO 256
#define HDIM 56
#define WDIM 56
#define HW 3136
#define NCOL 12544     // NB*HW
#define NHEAD 2
#define HD 128
#define EPS 1e-5f
#define SEH 16
#define NPAN 98        // NCOL/128
#define CHUNKW 2048    // u32 per 128x16 chunk image

// attention dynamic smem layout (floats)
#define KV_STRIDE 132
#define KV_ROWS 72
#define QB_OFF   (KV_ROWS * KV_STRIDE)          // 9504
#define AW_STRIDE 68
#define SS_OFF   (QB_OFF + 16 * KV_STRIDE)      // 11616
#define SS_STRIDE 76
#define SMEM_ATTN ((SS_OFF + 16 * SS_STRIDE) * 4)   // 51328 bytes

// ---------------- scratch (device globals, no allocation) ----------------
__device__ uint32_t g_Wp [4 * 2 * 16 * CHUNKW];   // weight A-panels (tf32 frag layout)
__device__ uint32_t g_xtp[NPAN * 16 * CHUNKW];    // x B-panels
__device__ uint32_t g_y1p[NPAN * 16 * CHUNKW];    // y1 B-panels
__device__ uint32_t g_y2p[NPAN * 16 * CHUNKW];    // y2 B-panels
__device__ float g_qt[NCOL * CO];   // [n][c]  (tf32-rounded)
__device__ float g_kt[NCOL * CO];
__device__ float g_vt[NCOL * CO];
__device__ float g_s [NB * SEH * HW]; // channel-major [b][j][hw]
__device__ float g_p [NB * SEH];
__device__ float g_g [NB * SEH];

// ---------------- helpers ----------------
__device__ __forceinline__ uint32_t f2tf32(float f) {
    uint32_t u;
    asm("cvt.rna.tf32.f32 %0, %1;" : "=r"(u) : "f"(f));
    return u;
}
__device__ __forceinline__ float f2tf32f(float f) {
    return __uint_as_float(f2tf32(f));
}
__device__ __forceinline__ void cpasync16(uint32_t smem, const void* g) {
    asm volatile("cp.async.cg.shared.global [%0], [%1], 16;" :: "r"(smem), "l"(g));
}
__device__ __forceinline__ uint32_t smem_u32x(const void* p) {
    uint32_t a;
    asm("{ .reg .u64 t; cvta.to.shared.u64 t, %1; cvt.u32.u64 %0, t; }" : "=r"(a) : "l"(p));
    return a;
}
__device__ __forceinline__ void mma_tf32(float* d, const uint32_t* a, const uint32_t* b) {
    asm volatile(
        "mma.sync.aligned.m16n8k8.row.col.f32.tf32.tf32.f32 "
        "{%0,%1,%2,%3}, {%4,%5,%6,%7}, {%8,%9}, {%0,%1,%2,%3};"
        : "+f"(d[0]), "+f"(d[1]), "+f"(d[2]), "+f"(d[3])
        : "r"(a[0]), "r"(a[1]), "r"(a[2]), "r"(a[3]), "r"(b[0]), "r"(b[1]));
}

// A-image u32 offset within one 128x16 chunk (m rows x k cols)
__device__ __forceinline__ int a_off(int m, int k) {
    int ks = k >> 3, mtile = m >> 4, mi = m & 15;
    int lane = (mi & 7) * 4 + (k & 3);
    int slot = (mi >> 3) + 2 * ((k >> 2) & 1);
    int I = (ks * 8 + mtile) * 32 + lane;
    I ^= (I >> 3) & 3;
    return I * 4 + slot;
}
// B-image u32 offset within one 128x16 chunk (n rows x k cols)
__device__ __forceinline__ int b_off(int n, int k) {
    int ks = k >> 3, ntile = n >> 3;
    int lane = (n & 7) * 4 + (k & 3);
    int slot = (k >> 2) & 1;
    int I = (ks * 16 + ntile) * 32 + lane;
    I ^= (I >> 4) & 3;
    return I * 2 + slot;
}

// ---------------- weight repack: 4 matrices -> A-panels (+ zero g_p) -------
__global__ void repack_w_kernel(const float* __restrict__ Wq, const float* __restrict__ Wk,
                                const float* __restrict__ Wv, const float* __restrict__ Wa) {
    if (blockIdx.x == 0 && threadIdx.x < NB * SEH) g_p[threadIdx.x] = 0.f;
    int v = blockIdx.x * 256 + threadIdx.x;    // 4*256*256 values
    int mat = v >> 16;
    int rem = v & 65535;
    int o = rem >> 8, c = rem & 255;
    const float* W = (mat == 0) ? Wq : (mat == 1 ? Wk : (mat == 2 ? Wv : Wa));
    uint32_t u = f2tf32(W[o * 256 + c]);
    g_Wp[(((size_t)mat * 2 + (o >> 7)) * 16 + (c >> 4)) * CHUNKW + a_off(o & 127, c & 15)] = u;
}

// ---------------- transpose x: [b][c][hw] -> B-panels ----------------
__global__ void transpose_x_kernel(const float* __restrict__ x) {
    __shared__ float t[32][33];
    int b = blockIdx.z;
    int c0 = blockIdx.y * 32, p0 = blockIdx.x * 32;
    int tx = threadIdx.x, ty = threadIdx.y;   // 32 x 8
    const float* xb = x + ((size_t)b * CIN + c0) * HW + p0;
#pragma unroll
    for (int i = 0; i < 4; i++)
        t[ty * 4 + i][tx] = xb[(size_t)(ty * 4 + i) * HW + tx];
    __syncthreads();
    int c = c0 + tx;
#pragma unroll
    for (int i = 0; i < 4; i++) {
        int nglob = b * HW + p0 + ty * 4 + i;
        int ntile = nglob >> 7, nn = nglob & 127;
        g_xtp[((size_t)ntile * 16 + (c >> 4)) * CHUNKW + b_off(nn, c & 15)]
            = f2tf32(t[tx][ty * 4 + i]);
    }
}

// ---------------- tensor-core tf32 GEMM, cp.async 3-stage, M128 x N128 -----
// mode 0: qkv (z selects matrix 0..2, B=g_xtp, out flat [n][c] tf32-rounded)
// mode 1: agg (matrix 3, B=g_y1p, out g_y2p panels with BN2, tf32-rounded)
__global__ __launch_bounds__(256, 2) void gemm_mma_kernel(
    const float* __restrict__ g2, const float* __restrict__ b2,
    const float* __restrict__ m2, const float* __restrict__ v2,
    int mode)
{
    __shared__ __align__(16) char smraw[49152];
    float* stg = (float*)smraw;

    int tid = threadIdx.x;
    int wid = tid >> 5, lane = tid & 31;
    int warpM = wid >> 2, warpN = wid & 3;
    int g = lane >> 2, t = lane & 3;

    int mat;
    const uint32_t* Bbase;
    float* outp = nullptr;
    if (mode == 0) {
        mat = blockIdx.z;
        Bbase = g_xtp;
        outp = (mat == 0) ? g_qt : (mat == 1 ? g_kt : g_vt);
    } else {
        mat = 3; Bbase = g_y1p;
    }
    int o0 = blockIdx.y * 128;
    int n0 = blockIdx.x * 128;

    const uint4* Apan = (const uint4*)&g_Wp[((size_t)mat * 2 + blockIdx.y) * 16 * CHUNKW];
    const uint4* Bpan = (const uint4*)&Bbase[(size_t)blockIdx.x * 16 * CHUNKW];
    uint32_t smb = smem_u32x(smraw);

    float acc[4][4][4];
#pragma unroll
    for (int i = 0; i < 4; i++)
#pragma unroll
        for (int j = 0; j < 4; j++)
#pragma unroll
            for (int s = 0; s < 4; s++) acc[i][j][s] = 0.f;

#define ISSUE(c, s) do { \
        uint32_t dst = smb + (s) * 16384; \
        const uint4* sa = Apan + (c) * 512; \
        const uint4* sb = Bpan + (c) * 512; \
        cpasync16(dst + tid * 16,                sa + tid); \
        cpasync16(dst + (tid + 256) * 16,        sa + tid + 256); \
        cpasync16(dst + 8192 + tid * 16,         sb + tid); \
        cpasync16(dst + 8192 + (tid + 256) * 16, sb + tid + 256); \
        asm volatile("cp.async.commit_group;"); \
    } while (0)

    ISSUE(0, 0);
    ISSUE(1, 1);

    for (int c = 0; c < 16; c++) {
        if (c < 15) asm volatile("cp.async.wait_group 1;");
        else        asm volatile("cp.async.wait_group 0;");
        __syncthreads();
        if (c + 2 < 16) ISSUE(c + 2, (c + 2) % 3);

        const uint4* Ab = (const uint4*)(smraw + (c % 3) * 16384);
        const uint2* Bb = (const uint2*)(smraw + (c % 3) * 16384 + 8192);
#pragma unroll
        for (int ks = 0; ks < 2; ks++) {
            uint32_t af[4][4], bf[4][2];
#pragma unroll
            for (int mt = 0; mt < 4; mt++) {
                int idx = (ks * 8 + warpM * 4 + mt) * 32 + lane;
                idx ^= (idx >> 3) & 3;
                uint4 v = Ab[idx];
                af[mt][0] = v.x; af[mt][1] = v.y; af[mt][2] = v.z; af[mt][3] = v.w;
            }
#pragma unroll
            for (int nt = 0; nt < 4; nt++) {
                int idx = (ks * 16 + warpN * 4 + nt) * 32 + lane;
                idx ^= (idx >> 4) & 3;
                uint2 v = Bb[idx];
                bf[nt][0] = v.x; bf[nt][1] = v.y;
            }
#pragma unroll
            for (int mt = 0; mt < 4; mt++)
#pragma unroll
                for (int nt = 0; nt < 4; nt++)
                    mma_tf32(acc[mt][nt], af[mt], bf[nt]);
        }
        __syncthreads();
    }
#undef ISSUE

    int h_of_warp = warpN >> 1;
    for (int h = 0; h < 2; h++) {
        __syncthreads();
        if (h_of_warp == h) {
#pragma unroll
            for (int mt = 0; mt < 4; mt++)
#pragma unroll
                for (int nt = 0; nt < 4; nt++)
#pragma unroll
                    for (int s = 0; s < 4; s++) {
                        int ol = warpM * 64 + mt * 16 + g + (s >> 1) * 8;
                        int nl = (warpN & 1) * 32 + nt * 8 + 2 * t + (s & 1);
                        stg[nl * 132 + ol] = acc[mt][nt][s];
                    }
        }
        __syncthreads();
#pragma unroll
        for (int i = 0; i < 8; i++) {
            int idx = tid + 256 * i;
            int nl = idx >> 5, o4 = idx & 31;
            float4 v = *(float4*)&stg[nl * 132 + o4 * 4];
            int nglob = n0 + h * 64 + nl;
            if (mode == 1) {
                int ob = o0 + o4 * 4;
                float4 gg = *(const float4*)&g2[ob];
                float4 bb = *(const float4*)&b2[ob];
                float4 mm = *(const float4*)&m2[ob];
                float4 vv = *(const float4*)&v2[ob];
                float s0 = gg.x * rsqrtf(vv.x + EPS);
                float s1 = gg.y * rsqrtf(vv.y + EPS);
                float s2 = gg.z * rsqrtf(vv.z + EPS);
                float s3 = gg.w * rsqrtf(vv.w + EPS);
                v.x = v.x * s0 + (bb.x - mm.x * s0);
                v.y = v.y * s1 + (bb.y - mm.y * s1);
                v.z = v.z * s2 + (bb.z - mm.z * s2);
                v.w = v.w * s3 + (bb.w - mm.w * s3);
                int pt = nglob >> 7, nn = nglob & 127;
                uint32_t* pb = &g_y2p[((size_t)pt * 16) * CHUNKW];
                const float* pv = &v.x;
#pragma unroll
                for (int j = 0; j < 4; j++) {
                    int ch = ob + j;
                    pb[(size_t)(ch >> 4) * CHUNKW + b_off(nn, ch & 15)] = f2tf32(pv[j]);
                }
            } else {
                // tf32-round here so attn can stage raw copies
                v.x = f2tf32f(v.x); v.y = f2tf32f(v.y);
                v.z = f2tf32f(v.z); v.w = f2tf32f(v.w);
                *(float4*)&outp[(size_t)nglob * 256 + o0 + o4 * 4] = v;
            }
        }
    }
}

// ---------------- attention: tensor-core (mma.sync tf32) --------------------
// q/k/v are already tf32-rounded in global; staging is a raw copy.
__global__ void attn_kernel(const float* __restrict__ rel_h,
                            const float* __restrict__ rel_w,
                            const float* __restrict__ g1, const float* __restrict__ b1,
                            const float* __restrict__ m1, const float* __restrict__ v1) {
    extern __shared__ float sm[];
    float* kv = sm;              // [72][132]  K' then V
    float* qb = sm + QB_OFF;     // [16][132]  Q, later attnw[16][68]
    float* sS = sm + SS_OFF;     // [16][76]   scores, later scl[128]/bo[128]

    int tid = threadIdx.x, wid = tid >> 5, lane = tid & 31;
    int g = lane >> 2, t4 = lane & 3;
    int tile = blockIdx.x;
    int th = tile / 14, tw = tile % 14;
    int nh = blockIdx.y, b = blockIdx.z;
    int h0 = th * 4, w0 = tw * 4;
    const float* rel = nh ? rel_w : rel_h;

    // ---- load Q (already tf32) ----
    const float* qbase = g_qt + (size_t)b * HW * CO + nh * HD;
#pragma unroll
    for (int i = 0; i < 2; i++) {
        int f = tid + 256 * i;
        int m = f >> 5, c4 = f & 31;
        int hw = (h0 + (m >> 2)) * WDIM + w0 + (m & 3);
        *(float4*)&qb[m * KV_STRIDE + c4 * 4] =
            *(const float4*)&qbase[(size_t)hw * CO + c4 * 4];
    }
    // ---- load K halo ----
    const float* kbase = g_kt + (size_t)b * HW * CO + nh * HD;
#pragma unroll
    for (int i = 0; i < 8; i++) {
        int f = tid + 256 * i;
        int pos = f >> 5, c4 = f & 31;
        int hh = h0 - 2 + (pos >> 3), ww = w0 - 2 + (pos & 7);
        float4 v = make_float4(0.f, 0.f, 0.f, 0.f);
        if ((unsigned)hh < HDIM && (unsigned)ww < WDIM)
            v = *(const float4*)&kbase[(size_t)(hh * WDIM + ww) * CO + c4 * 4];
        *(float4*)&kv[pos * KV_STRIDE + c4 * 4] = v;
    }
    // ---- rel rows 64..68, zeros 69..71 ----
    {
        int pos = 64 + (tid >> 5), c4 = tid & 31;
        float4 r = make_float4(0.f, 0.f, 0.f, 0.f);
        if (pos < 69) {
            int tp = pos - 64;
            r.x = f2tf32f(rel[(c4 * 4 + 0) * 5 + tp]);
            r.y = f2tf32f(rel[(c4 * 4 + 1) * 5 + tp]);
            r.z = f2tf32f(rel[(c4 * 4 + 2) * 5 + tp]);
            r.w = f2tf32f(rel[(c4 * 4 + 3) * 5 + tp]);
        }
        *(float4*)&kv[pos * KV_STRIDE + c4 * 4] = r;
    }
    __syncthreads();

    // ---- scores mma ----
    float accS0[4] = {0.f, 0.f, 0.f, 0.f};
    float accS1[4] = {0.f, 0.f, 0.f, 0.f};
#pragma unroll
    for (int ks = 0; ks < 16; ks++) {
        int kk = ks * 8 + t4;
        uint32_t a[4];
        a[0] = __float_as_uint(qb[g * KV_STRIDE + kk]);
        a[1] = __float_as_uint(qb[(g + 8) * KV_STRIDE + kk]);
        a[2] = __float_as_uint(qb[g * KV_STRIDE + kk + 4]);
        a[3] = __float_as_uint(qb[(g + 8) * KV_STRIDE + kk + 4]);
        uint32_t bb[2];
        bb[0] = __float_as_uint(kv[(wid * 8 + g) * KV_STRIDE + kk]);
        bb[1] = __float_as_uint(kv[(wid * 8 + g) * KV_STRIDE + kk + 4]);
        mma_tf32(accS0, a, bb);
        if (wid == 0) {
            uint32_t b2r[2];
            b2r[0] = __float_as_uint(kv[(64 + g) * KV_STRIDE + kk]);
            b2r[1] = __float_as_uint(kv[(64 + g) * KV_STRIDE + kk + 4]);
            mma_tf32(accS1, a, b2r);
        }
    }
#pragma unroll
    for (int s = 0; s < 4; s++) {
        int m = g + (s >> 1) * 8;
        sS[m * SS_STRIDE + wid * 8 + 2 * t4 + (s & 1)] = accS0[s];
        if (wid == 0) sS[m * SS_STRIDE + 64 + 2 * t4 + (s & 1)] = accS1[s];
    }
    __syncthreads();

    // ---- load V over kv rows 0..63 ----
    const float* vbase = g_vt + (size_t)b * HW * CO + nh * HD;
#pragma unroll
    for (int i = 0; i < 8; i++) {
        int f = tid + 256 * i;
        int pos = f >> 5, c4 = f & 31;
        int hh = h0 - 2 + (pos >> 3), ww = w0 - 2 + (pos & 7);
        float4 v = make_float4(0.f, 0.f, 0.f, 0.f);
        if ((unsigned)hh < HDIM && (unsigned)ww < WDIM)
            v = *(const float4*)&vbase[(size_t)(hh * WDIM + ww) * CO + c4 * 4];
        *(float4*)&kv[pos * KV_STRIDE + c4 * 4] = v;
    }

    // ---- softmax ----
#pragma unroll
    for (int pp = 0; pp < 2; pp++) {
        int pi = wid * 2 + pp;
        int py = pi >> 2, px = pi & 3;
        float scv = -1e30f;
        int pos = 0;
        if (lane < 25) {
            int ki = lane / 5, kj = lane % 5;
            pos = (py + ki) * 8 + (px + kj);
            float bias = sS[pi * SS_STRIDE + 64 + (nh ? kj : ki)];
            scv = (sS[pi * SS_STRIDE + pos] + bias) * 0.08838834764831845f;
        }
        float mx = scv;
#pragma unroll
        for (int m = 16; m; m >>= 1) mx = fmaxf(mx, __shfl_xor_sync(0xffffffffu, mx, m));
        float e = (lane < 25) ? __expf(scv - mx) : 0.f;
        float ssum = e;
#pragma unroll
        for (int m = 16; m; m >>= 1) ssum += __shfl_xor_sync(0xffffffffu, ssum, m);
        float wv = e / ssum;
        float* aw = qb;
        aw[pi * AW_STRIDE + lane] = 0.f;
        aw[pi * AW_STRIDE + 32 + lane] = 0.f;
        if (lane < 25) aw[pi * AW_STRIDE + pos] = f2tf32f(wv);
    }
    __syncthreads();

    // ---- BN1 scale/bias into sS ----
    if (tid < 128) {
        int ch = nh * HD + tid;
        float scl = g1[ch] * rsqrtf(v1[ch] + EPS);
        sS[tid] = scl;
        sS[128 + tid] = b1[ch] - m1[ch] * scl;
    }

    // ---- AV mma ----
    float accV0[4] = {0.f, 0.f, 0.f, 0.f};
    float accV1[4] = {0.f, 0.f, 0.f, 0.f};
#pragma unroll
    for (int ks = 0; ks < 8; ks++) {
        int kk = ks * 8 + t4;
        uint32_t a[4];
        a[0] = __float_as_uint(qb[g * AW_STRIDE + kk]);
        a[1] = __float_as_uint(qb[(g + 8) * AW_STRIDE + kk]);
        a[2] = __float_as_uint(qb[g * AW_STRIDE + kk + 4]);
        a[3] = __float_as_uint(qb[(g + 8) * AW_STRIDE + kk + 4]);
        uint32_t bb[2];
        int c0 = wid * 16 + g;
        bb[0] = __float_as_uint(kv[kk * KV_STRIDE + c0]);
        bb[1] = __float_as_uint(kv[(kk + 4) * KV_STRIDE + c0]);
        mma_tf32(accV0, a, bb);
        bb[0] = __float_as_uint(kv[kk * KV_STRIDE + c0 + 8]);
        bb[1] = __float_as_uint(kv[(kk + 4) * KV_STRIDE + c0 + 8]);
        mma_tf32(accV1, a, bb);
    }
    __syncthreads();

    // ---- epilogue: BN1 + relu -> g_y1p panels ----
#pragma unroll
    for (int j = 0; j < 2; j++) {
        const float* acc = j ? accV1 : accV0;
        int ntc = wid * 2 + j;
#pragma unroll
        for (int s = 0; s < 4; s++) {
            int m = g + (s >> 1) * 8;
            int c = ntc * 8 + 2 * t4 + (s & 1);
            int ch = nh * HD + c;
            int hw = (h0 + (m >> 2)) * WDIM + w0 + (m & 3);
            int nglob = b * HW + hw;
            float val = fmaxf(acc[s] * sS[c] + sS[128 + c], 0.f);
            g_y1p[((size_t)(nglob >> 7) * 16 + (ch >> 4)) * CHUNKW + b_off(nglob & 127, ch & 15)]
                = f2tf32(val);
        }
    }
}

// ---------------- SE stage 1: mma over y2 panels ----------------
__global__ __launch_bounds__(256) void se1_kernel(const float* __restrict__ Win,
                           const float* __restrict__ gin, const float* __restrict__ bin,
                           const float* __restrict__ min_, const float* __restrict__ vin) {
    __shared__ uint32_t Wf[4096];
    __shared__ float bnscl[SEH], bnbo[SEH];
    __shared__ float pool[2][SEH];
    int tid = threadIdx.x, wid = tid >> 5, lane = tid & 31;
    int g = lane >> 2, t4 = lane & 3;

#pragma unroll
    for (int it = 0; it < 16; it++) {
        int i = tid + 256 * it;
        int m = i >> 8, k = i & 255;
        int kc = k >> 4, ks = (k >> 3) & 1;
        int laneA = (m & 7) * 4 + (k & 3);
        int slot = (m >> 3) + 2 * ((k >> 2) & 1);
        Wf[((kc * 2 + ks) * 32 + laneA) * 4 + slot] = f2tf32(Win[m * 256 + k]);
    }
    if (tid < SEH) {
        float scl = gin[tid] * rsqrtf(vin[tid] + EPS);
        bnscl[tid] = scl;
        bnbo[tid] = bin[tid] - min_[tid] * scl;
        pool[0][tid] = 0.f;
        pool[1][tid] = 0.f;
    }
    __syncthreads();

    int panel = blockIdx.x;
    const uint32_t* Bpan = g_y2p + (size_t)panel * 16 * CHUNKW;

    float acc[2][4];
#pragma unroll
    for (int nt = 0; nt < 2; nt++)
#pragma unroll
        for (int s = 0; s < 4; s++) acc[nt][s] = 0.f;

#pragma unroll
    for (int kc = 0; kc < 16; kc++) {
#pragma unroll
        for (int ks = 0; ks < 2; ks++) {
            uint4 av = ((const uint4*)Wf)[(kc * 2 + ks) * 32 + lane];
            uint32_t a[4] = {av.x, av.y, av.z, av.w};
#pragma unroll
            for (int nt = 0; nt < 2; nt++) {
                int ntile = wid * 2 + nt;
                int idx = (ks * 16 + ntile) * 32 + lane;
                idx ^= (idx >> 4) & 3;
                uint2 bv = *(const uint2*)(Bpan + (size_t)kc * CHUNKW + idx * 2);
                uint32_t bb[2] = {bv.x, bv.y};
                mma_tf32(acc[nt], a, bb);
            }
        }
    }

    int b_first = (panel * 128) / HW;
#pragma unroll
    for (int nt = 0; nt < 2; nt++) {
        int ntile = wid * 2 + nt;
#pragma unroll
        for (int s = 0; s < 4; s++) {
            int j = g + (s >> 1) * 8;
            int pix = ntile * 8 + 2 * t4 + (s & 1);
            int nglob = panel * 128 + pix;
            int b = nglob / HW, hw = nglob % HW;
            float sv = fmaxf(acc[nt][s] * bnscl[j] + bnbo[j], 0.f);
            g_s[(size_t)b * SEH * HW + (size_t)j * HW + hw] = sv;
            atomicAdd(&pool[b - b_first][j], sv);
        }
    }
    __syncthreads();
    if (tid < 2 * SEH) {
        int bl = tid >> 4, j = tid & 15;
        int b = b_first + bl;
        if (b < NB) atomicAdd(&g_p[b * SEH + j], pool[bl][j]);
    }
}

// ---------------- SE stage 2 ----------------
__global__ void se2_kernel(const float* __restrict__ fc1, const float* __restrict__ fc2) {
    int tid = threadIdx.x;
    if (tid < NB * SEH) {
        int bb = tid >> 4, i = tid & 15;
        float hsum = 0.f;
#pragma unroll
        for (int j = 0; j < SEH; j++) hsum += (g_p[bb * SEH + j] * (1.f / HW)) * fc1[j];
        float hid = fmaxf(hsum, 0.f);
        g_g[tid] = 1.f / (1.f + __expf(-(hid * fc2[i])));
    }
}

// ---------------- SE stage 3 ----------------
__global__ void se3_kernel(const float* __restrict__ Wout,
                           const float* __restrict__ gout, const float* __restrict__ bout,
                           const float* __restrict__ mout, const float* __restrict__ vout,
                           float* __restrict__ out) {
    __shared__ float sjs[SEH][16];
    int tid = threadIdx.x;
    int n0 = blockIdx.x * 16;
    int bb = n0 / HW;
    int hw0 = n0 % HW;

    int j = tid >> 4, nn = tid & 15;
    sjs[j][nn] = g_s[(size_t)bb * SEH * HW + (size_t)j * HW + hw0 + nn] * g_g[bb * SEH + j];
    __syncthreads();

    int o = tid;
    float wreg[SEH];
#pragma unroll
    for (int jj = 0; jj < SEH; jj++) wreg[jj] = Wout[o * SEH + jj];
    float scl = gout[o] * rsqrtf(vout[o] + EPS);
    float bo = bout[o] - mout[o] * scl;
    float* op = out + (size_t)bb * CO * HW + (size_t)o * HW + hw0;
#pragma unroll
    for (int nq = 0; nq < 4; nq++) {
        float4 a = make_float4(0.f, 0.f, 0.f, 0.f);
#pragma unroll
        for (int jj = 0; jj < SEH; jj++) {
            float wv = wreg[jj];
            a.x += wv * sjs[jj][nq * 4 + 0];
            a.y += wv * sjs[jj][nq * 4 + 1];
            a.z += wv * sjs[jj][nq * 4 + 2];
            a.w += wv * sjs[jj][nq * 4 + 3];
        }
        float4 r;
        r.x = a.x * scl + bo; r.y = a.y * scl + bo;
        r.z = a.z * scl + bo; r.w = a.w * scl + bo;
        *(float4*)&op[nq * 4] = r;
    }
}

// ---------------- launch ----------------
extern "C" void kernel_launch(void* const* d_in, const int* in_sizes, int n_in,
                              void* d_out, int out_size) {
    const float* x       = (const float*)d_in[0];
    const float* Wq      = (const float*)d_in[1];
    const float* Wk      = (const float*)d_in[2];
    const float* Wv      = (const float*)d_in[3];
    const float* rel_h   = (const float*)d_in[4];
    const float* rel_w   = (const float*)d_in[5];
    const float* agg_g1  = (const float*)d_in[6];
    const float* agg_b1  = (const float*)d_in[7];
    const float* agg_m1  = (const float*)d_in[8];
    const float* agg_v1  = (const float*)d_in[9];
    const float* agg_W   = (const float*)d_in[10];
    const float* agg_g2  = (const float*)d_in[11];
    const float* agg_b2  = (const float*)d_in[12];
    const float* agg_m2  = (const float*)d_in[13];
    const float* agg_v2  = (const float*)d_in[14];
    const float* se_Win  = (const float*)d_in[15];
    const float* se_g_in = (const float*)d_in[16];
    const float* se_b_in = (const float*)d_in[17];
    const float* se_m_in = (const float*)d_in[18];
    const float* se_v_in = (const float*)d_in[19];
    const float* se_fc1  = (const float*)d_in[20];
    const float* se_fc2  = (const float*)d_in[21];
    const float* se_Wout = (const float*)d_in[22];
    const float* se_g_out= (const float*)d_in[23];
    const float* se_b_out= (const float*)d_in[24];
    const float* se_m_out= (const float*)d_in[25];
    const float* se_v_out= (const float*)d_in[26];
    float* out = (float*)d_out;

    cudaFuncSetAttribute(attn_kernel,
                         cudaFuncAttributeMaxDynamicSharedMemorySize, SMEM_ATTN);

    repack_w_kernel<<<1024, 256>>>(Wq, Wk, Wv, agg_W);
    transpose_x_kernel<<<dim3(98, 8, 4), dim3(32, 8)>>>(x);

    gemm_mma_kernel<<<dim3(98, 2, 3), 256>>>(nullptr, nullptr, nullptr, nullptr, 0);

    attn_kernel<<<dim3(196, NHEAD, NB), 256, SMEM_ATTN>>>(rel_h, rel_w,
                                                          agg_g1, agg_b1, agg_m1, agg_v1);

    gemm_mma_kernel<<<dim3(98, 2, 1), 256>>>(agg_g2, agg_b2, agg_m2, agg_v2, 1);

    se1_kernel<<<NPAN, 256>>>(se_Win, se_g_in, se_b_in, se_m_in, se_v_in);
    se2_kernel<<<1, 64>>>(se_fc1, se_fc2);
    se3_kernel<<<NCOL / 16, 256>>>(se_Wout, se_g_out, se_b_out, se_m_out, se_v_out, out);
}